// round 2
// baseline (speedup 1.0000x reference)
#include <cuda_runtime.h>
#include <math.h>

#define BN_EPS 1e-5f

// ---------------- scratch (device globals; no allocation allowed) ----------------
__device__ float g_h1[4096 * 32 * 16 * 16];   // 128 MB  [B,32,16,16]
__device__ float g_h2[4096 * 64 * 8 * 8];     //  64 MB  [B,64,8,8]
__device__ float g_feat[4096 * 128];          //   2 MB  [B,128]

// =============================================================================
// Stage 1: conv(3->32, 3x3 SAME) + bias + BN + ReLU + 2x2 maxpool
// in: x [B,3,32,32]  out: g_h1 [B,32,16,16]
// grid = B, block = 256
// =============================================================================
__global__ __launch_bounds__(256) void conv1_kernel(
    const float* __restrict__ x,
    const float* __restrict__ w,     // [32,3,3,3]
    const float* __restrict__ bias,
    const float* __restrict__ gam,
    const float* __restrict__ bet,
    const float* __restrict__ mean,
    const float* __restrict__ var)
{
    __shared__ float s_in[3][34][35];   // zero-padded (pad=1), col stride 35
    __shared__ float s_w[32 * 27];
    __shared__ float s_scale[32], s_shift[32];

    const int b = blockIdx.x;
    const int tid = threadIdx.x;
    const float* xb = x + (size_t)b * 3 * 32 * 32;

    for (int i = tid; i < 3 * 34 * 34; i += 256) {
        int c = i / (34 * 34);
        int r = (i / 34) % 34;
        int cc = i % 34;
        float v = 0.f;
        if (r >= 1 && r <= 32 && cc >= 1 && cc <= 32)
            v = xb[c * 1024 + (r - 1) * 32 + (cc - 1)];
        s_in[c][r][cc] = v;
    }
    for (int i = tid; i < 32 * 27; i += 256) s_w[i] = w[i];
    if (tid < 32) {
        float inv = gam[tid] * rsqrtf(var[tid] + BN_EPS);
        s_scale[tid] = inv;
        s_shift[tid] = (bias[tid] - mean[tid]) * inv + bet[tid];
    }
    __syncthreads();

    float* ob = g_h1 + (size_t)b * 32 * 256;

    // 1024 work items = 32 oc x 16 pooled-rows x 2 halves; 4 per thread
    for (int rep = 0; rep < 4; rep++) {
        int wk = tid + rep * 256;
        int oc = wk >> 5;
        int rem = wk & 31;
        int py = rem >> 1;
        int half = rem & 1;
        int x0 = half * 16;          // conv-col base (padded col base = x0)
        int r0 = 2 * py;             // padded row base (covers 4 rows)

        float acc0[16], acc1[16];
        #pragma unroll
        for (int i = 0; i < 16; i++) { acc0[i] = 0.f; acc1[i] = 0.f; }

        for (int ic = 0; ic < 3; ic++) {
            float wr[9];
            #pragma unroll
            for (int k = 0; k < 9; k++) wr[k] = s_w[oc * 27 + ic * 9 + k];

            float c0[4], c1[4];
            #pragma unroll
            for (int dy = 0; dy < 4; dy++) {
                c0[dy] = s_in[ic][r0 + dy][x0];
                c1[dy] = s_in[ic][r0 + dy][x0 + 1];
            }
            #pragma unroll
            for (int cx = 0; cx < 16; cx++) {
                float c2[4];
                #pragma unroll
                for (int dy = 0; dy < 4; dy++) c2[dy] = s_in[ic][r0 + dy][x0 + cx + 2];
                acc0[cx] += (wr[0] * c0[0] + wr[1] * c1[0] + wr[2] * c2[0])
                          + (wr[3] * c0[1] + wr[4] * c1[1] + wr[5] * c2[1])
                          + (wr[6] * c0[2] + wr[7] * c1[2] + wr[8] * c2[2]);
                acc1[cx] += (wr[0] * c0[1] + wr[1] * c1[1] + wr[2] * c2[1])
                          + (wr[3] * c0[2] + wr[4] * c1[2] + wr[5] * c2[2])
                          + (wr[6] * c0[3] + wr[7] * c1[3] + wr[8] * c2[3]);
                #pragma unroll
                for (int dy = 0; dy < 4; dy++) { c0[dy] = c1[dy]; c1[dy] = c2[dy]; }
            }
        }
        float sc = s_scale[oc], sh = s_shift[oc];
        #pragma unroll
        for (int px = 0; px < 8; px++) {
            float v00 = fmaxf(fmaf(acc0[2 * px],     sc, sh), 0.f);
            float v01 = fmaxf(fmaf(acc0[2 * px + 1], sc, sh), 0.f);
            float v10 = fmaxf(fmaf(acc1[2 * px],     sc, sh), 0.f);
            float v11 = fmaxf(fmaf(acc1[2 * px + 1], sc, sh), 0.f);
            ob[oc * 256 + py * 16 + half * 8 + px] =
                fmaxf(fmaxf(v00, v01), fmaxf(v10, v11));
        }
    }
}

// =============================================================================
// Stage 2: conv(32->64) + bias + BN + ReLU + pool
// in: g_h1 [B,32,16,16]  out: g_h2 [B,64,8,8]
// grid = B*8 (8 oc-groups of 8), block = 128
// =============================================================================
__global__ __launch_bounds__(128) void conv2_kernel(
    const float* __restrict__ w,     // [64,32,3,3]
    const float* __restrict__ bias,
    const float* __restrict__ gam,
    const float* __restrict__ bet,
    const float* __restrict__ mean,
    const float* __restrict__ var)
{
    __shared__ float s_in[32][16][19]; // cols padded: idx = input col + 1; 0 and 17 are zero
    __shared__ float s_w[2304];        // 8 oc x 32 ic x 9

    const int b = blockIdx.x >> 3;
    const int oc_base = (blockIdx.x & 7) * 8;
    const int tid = threadIdx.x;
    const float* ib = g_h1 + (size_t)b * 8192;

    for (int i = tid; i < 32 * 16 * 19; i += 128) {
        int ic = i / 304;
        int rr = (i / 19) % 16;
        int c = i % 19;
        float v = 0.f;
        if (c >= 1 && c <= 16) v = ib[ic * 256 + rr * 16 + (c - 1)];
        s_in[ic][rr][c] = v;
    }
    for (int i = tid; i < 2304; i += 128) s_w[i] = w[oc_base * 288 + i];
    __syncthreads();

    const int oc_l = tid >> 4;
    const int py = (tid >> 1) & 7;
    const int half = tid & 1;
    const int x0 = half * 8;           // padded col base
    const int rbase = 2 * py - 1;
    const float m0 = (py > 0) ? 1.f : 0.f;
    const float m3 = (py < 7) ? 1.f : 0.f;
    const int r0 = (py > 0) ? rbase : 0;
    const int r1 = rbase + 1, r2 = rbase + 2;
    const int r3 = (py < 7) ? rbase + 3 : 0;

    float acc0[8], acc1[8];
    #pragma unroll
    for (int i = 0; i < 8; i++) { acc0[i] = 0.f; acc1[i] = 0.f; }

    for (int ic = 0; ic < 32; ic++) {
        float wr[9];
        #pragma unroll
        for (int k = 0; k < 9; k++) wr[k] = s_w[oc_l * 288 + ic * 9 + k];

        float c0[4], c1[4];
        c0[0] = m0 * s_in[ic][r0][x0];  c1[0] = m0 * s_in[ic][r0][x0 + 1];
        c0[1] =      s_in[ic][r1][x0];  c1[1] =      s_in[ic][r1][x0 + 1];
        c0[2] =      s_in[ic][r2][x0];  c1[2] =      s_in[ic][r2][x0 + 1];
        c0[3] = m3 * s_in[ic][r3][x0];  c1[3] = m3 * s_in[ic][r3][x0 + 1];
        #pragma unroll
        for (int cx = 0; cx < 8; cx++) {
            float c2[4];
            c2[0] = m0 * s_in[ic][r0][x0 + cx + 2];
            c2[1] =      s_in[ic][r1][x0 + cx + 2];
            c2[2] =      s_in[ic][r2][x0 + cx + 2];
            c2[3] = m3 * s_in[ic][r3][x0 + cx + 2];
            acc0[cx] += (wr[0] * c0[0] + wr[1] * c1[0] + wr[2] * c2[0])
                      + (wr[3] * c0[1] + wr[4] * c1[1] + wr[5] * c2[1])
                      + (wr[6] * c0[2] + wr[7] * c1[2] + wr[8] * c2[2]);
            acc1[cx] += (wr[0] * c0[1] + wr[1] * c1[1] + wr[2] * c2[1])
                      + (wr[3] * c0[2] + wr[4] * c1[2] + wr[5] * c2[2])
                      + (wr[6] * c0[3] + wr[7] * c1[3] + wr[8] * c2[3]);
            #pragma unroll
            for (int dy = 0; dy < 4; dy++) { c0[dy] = c1[dy]; c1[dy] = c2[dy]; }
        }
    }

    const int oc = oc_base + oc_l;
    float inv = gam[oc] * rsqrtf(var[oc] + BN_EPS);
    float sh = (bias[oc] - mean[oc]) * inv + bet[oc];
    float* ob = g_h2 + (size_t)b * 4096 + oc * 64 + py * 8 + half * 4;
    #pragma unroll
    for (int px = 0; px < 4; px++) {
        float v00 = fmaxf(fmaf(acc0[2 * px],     inv, sh), 0.f);
        float v01 = fmaxf(fmaf(acc0[2 * px + 1], inv, sh), 0.f);
        float v10 = fmaxf(fmaf(acc1[2 * px],     inv, sh), 0.f);
        float v11 = fmaxf(fmaf(acc1[2 * px + 1], inv, sh), 0.f);
        ob[px] = fmaxf(fmaxf(v00, v01), fmaxf(v10, v11));
    }
}

// =============================================================================
// Stage 3: conv(64->128) + bias + BN + ReLU + pool + global 4x4 avgpool
// in: g_h2 [B,64,8,8]  out: g_feat [B,128]
// grid = B*16 (16 oc-groups of 8), block = 128 (4 ic-quarters x 8 oc x 4 rows)
// =============================================================================
__global__ __launch_bounds__(128) void conv3_kernel(
    const float* __restrict__ w,     // [128,64,3,3]
    const float* __restrict__ bias,
    const float* __restrict__ gam,
    const float* __restrict__ bet,
    const float* __restrict__ mean,
    const float* __restrict__ var)
{
    __shared__ float s_in[64][8][10];     // col-padded
    __shared__ float s_w[4608];           // 8 oc x 64 ic x 9
    __shared__ float s_part[4][8][4][16]; // [icq][oc][py][2rows x 8cols]
    __shared__ float s_psum[8][4];

    const int b = blockIdx.x >> 4;
    const int oc_base = (blockIdx.x & 15) * 8;
    const int tid = threadIdx.x;
    const float* ib = g_h2 + (size_t)b * 4096;

    for (int i = tid; i < 64 * 8 * 10; i += 128) {
        int ic = i / 80;
        int rr = (i / 10) % 8;
        int c = i % 10;
        float v = 0.f;
        if (c >= 1 && c <= 8) v = ib[ic * 64 + rr * 8 + (c - 1)];
        s_in[ic][rr][c] = v;
    }
    for (int i = tid; i < 4608; i += 128) s_w[i] = w[oc_base * 576 + i];
    __syncthreads();

    const int icq = tid >> 5;
    const int oc_l = (tid >> 2) & 7;
    const int py = tid & 3;
    const int rbase = 2 * py - 1;
    const float m0 = (py > 0) ? 1.f : 0.f;
    const float m3 = (py < 3) ? 1.f : 0.f;
    const int r0 = (py > 0) ? rbase : 0;
    const int r1 = rbase + 1, r2 = rbase + 2;
    const int r3 = (py < 3) ? rbase + 3 : 0;

    float acc0[8], acc1[8];
    #pragma unroll
    for (int i = 0; i < 8; i++) { acc0[i] = 0.f; acc1[i] = 0.f; }

    for (int ici = 0; ici < 16; ici++) {
        int ic = icq * 16 + ici;
        float wr[9];
        #pragma unroll
        for (int k = 0; k < 9; k++) wr[k] = s_w[oc_l * 576 + ic * 9 + k];

        float c0[4], c1[4];
        c0[0] = m0 * s_in[ic][r0][0];  c1[0] = m0 * s_in[ic][r0][1];
        c0[1] =      s_in[ic][r1][0];  c1[1] =      s_in[ic][r1][1];
        c0[2] =      s_in[ic][r2][0];  c1[2] =      s_in[ic][r2][1];
        c0[3] = m3 * s_in[ic][r3][0];  c1[3] = m3 * s_in[ic][r3][1];
        #pragma unroll
        for (int cx = 0; cx < 8; cx++) {
            float c2[4];
            c2[0] = m0 * s_in[ic][r0][cx + 2];
            c2[1] =      s_in[ic][r1][cx + 2];
            c2[2] =      s_in[ic][r2][cx + 2];
            c2[3] = m3 * s_in[ic][r3][cx + 2];
            acc0[cx] += (wr[0] * c0[0] + wr[1] * c1[0] + wr[2] * c2[0])
                      + (wr[3] * c0[1] + wr[4] * c1[1] + wr[5] * c2[1])
                      + (wr[6] * c0[2] + wr[7] * c1[2] + wr[8] * c2[2]);
            acc1[cx] += (wr[0] * c0[1] + wr[1] * c1[1] + wr[2] * c2[1])
                      + (wr[3] * c0[2] + wr[4] * c1[2] + wr[5] * c2[2])
                      + (wr[6] * c0[3] + wr[7] * c1[3] + wr[8] * c2[3]);
            #pragma unroll
            for (int dy = 0; dy < 4; dy++) { c0[dy] = c1[dy]; c1[dy] = c2[dy]; }
        }
    }

    #pragma unroll
    for (int i = 0; i < 8; i++) {
        s_part[icq][oc_l][py][i] = acc0[i];
        s_part[icq][oc_l][py][8 + i] = acc1[i];
    }
    __syncthreads();

    if (icq == 0) {
        const int oc = oc_base + oc_l;
        float inv = gam[oc] * rsqrtf(var[oc] + BN_EPS);
        float sh = (bias[oc] - mean[oc]) * inv + bet[oc];
        float sum = 0.f;
        #pragma unroll
        for (int px = 0; px < 4; px++) {
            float a00 = s_part[0][oc_l][py][2 * px]     + s_part[1][oc_l][py][2 * px]
                      + s_part[2][oc_l][py][2 * px]     + s_part[3][oc_l][py][2 * px];
            float a01 = s_part[0][oc_l][py][2 * px + 1] + s_part[1][oc_l][py][2 * px + 1]
                      + s_part[2][oc_l][py][2 * px + 1] + s_part[3][oc_l][py][2 * px + 1];
            float a10 = s_part[0][oc_l][py][8 + 2 * px]     + s_part[1][oc_l][py][8 + 2 * px]
                      + s_part[2][oc_l][py][8 + 2 * px]     + s_part[3][oc_l][py][8 + 2 * px];
            float a11 = s_part[0][oc_l][py][8 + 2 * px + 1] + s_part[1][oc_l][py][8 + 2 * px + 1]
                      + s_part[2][oc_l][py][8 + 2 * px + 1] + s_part[3][oc_l][py][8 + 2 * px + 1];
            float v00 = fmaxf(fmaf(a00, inv, sh), 0.f);
            float v01 = fmaxf(fmaf(a01, inv, sh), 0.f);
            float v10 = fmaxf(fmaf(a10, inv, sh), 0.f);
            float v11 = fmaxf(fmaf(a11, inv, sh), 0.f);
            sum += fmaxf(fmaxf(v00, v01), fmaxf(v10, v11));
        }
        s_psum[oc_l][py] = sum;
    }
    __syncthreads();

    if (tid < 8) {
        g_feat[(size_t)b * 128 + oc_base + tid] =
            (s_psum[tid][0] + s_psum[tid][1] + s_psum[tid][2] + s_psum[tid][3]) * (1.f / 16.f);
    }
}

// =============================================================================
// Stage 4: gate (top-2 softmax) + top-2 expert MLPs, fused.
// in: g_feat [B,128], out: d_out [B,10]
// grid = B/8, block = 256 (1 warp per sample)
// =============================================================================
__global__ __launch_bounds__(256) void moe_kernel(
    const float* __restrict__ w1,   // [8,128,64]
    const float* __restrict__ b1,   // [8,64]
    const float* __restrict__ w2,   // [8,64,10]
    const float* __restrict__ b2,   // [8,10]
    const float* __restrict__ gw,   // [128,8]
    const float* __restrict__ gb,   // [8]
    float* __restrict__ out, int B)
{
    __shared__ float s_feat[8][128];
    __shared__ float s_h[8][64];
    __shared__ float s_log[8][8];

    const int warp = threadIdx.x >> 5;
    const int lane = threadIdx.x & 31;
    const int s = blockIdx.x * 8 + warp;
    if (s >= B) return;

    for (int i = lane; i < 128; i += 32) s_feat[warp][i] = g_feat[(size_t)s * 128 + i];
    __syncwarp();

    if (lane < 8) {
        float a = gb[lane];
        for (int f = 0; f < 128; f++) a += s_feat[warp][f] * gw[f * 8 + lane];
        s_log[warp][lane] = a;
    }
    __syncwarp();

    // top-2 (computed redundantly in all lanes; matches lax.top_k tie semantics)
    float lg[8];
    #pragma unroll
    for (int e = 0; e < 8; e++) lg[e] = s_log[warp][e];
    int i0 = 0; float v0 = lg[0];
    #pragma unroll
    for (int e = 1; e < 8; e++) if (lg[e] > v0) { v0 = lg[e]; i0 = e; }
    int i1 = -1; float v1 = -3.402823466e38f;
    #pragma unroll
    for (int e = 0; e < 8; e++) if (e != i0 && lg[e] > v1) { v1 = lg[e]; i1 = e; }
    float e1 = expf(v1 - v0);
    float invs = 1.f / (1.f + e1);
    float wts[2] = { invs, e1 * invs };
    int eidx[2] = { i0, i1 };

    float outk = 0.f;
    for (int t = 0; t < 2; t++) {
        const int e = eidx[t];
        const float* w1e = w1 + (size_t)e * 128 * 64;
        float h0 = b1[e * 64 + lane];
        float h1v = b1[e * 64 + lane + 32];
        for (int f = 0; f < 128; f++) {
            float fv = s_feat[warp][f];
            h0  += fv * w1e[f * 64 + lane];
            h1v += fv * w1e[f * 64 + lane + 32];
        }
        s_h[warp][lane] = fmaxf(h0, 0.f);
        s_h[warp][lane + 32] = fmaxf(h1v, 0.f);
        __syncwarp();
        if (lane < 10) {
            const float* w2e = w2 + e * 640;
            float o = b2[e * 10 + lane];
            for (int j = 0; j < 64; j++) o += s_h[warp][j] * w2e[j * 10 + lane];
            outk += wts[t] * o;
        }
        __syncwarp();
    }
    if (lane < 10) out[(size_t)s * 10 + lane] = outk;
}

// =============================================================================
extern "C" void kernel_launch(void* const* d_in, const int* in_sizes, int n_in,
                              void* d_out, int out_size)
{
    const float* x       = (const float*)d_in[0];
    const float* c1w     = (const float*)d_in[1];
    const float* c1b     = (const float*)d_in[2];
    const float* bn1g    = (const float*)d_in[3];
    const float* bn1b    = (const float*)d_in[4];
    const float* bn1m    = (const float*)d_in[5];
    const float* bn1v    = (const float*)d_in[6];
    const float* c2w     = (const float*)d_in[7];
    const float* c2b     = (const float*)d_in[8];
    const float* bn2g    = (const float*)d_in[9];
    const float* bn2b    = (const float*)d_in[10];
    const float* bn2m    = (const float*)d_in[11];
    const float* bn2v    = (const float*)d_in[12];
    const float* c3w     = (const float*)d_in[13];
    const float* c3b     = (const float*)d_in[14];
    const float* bn3g    = (const float*)d_in[15];
    const float* bn3b    = (const float*)d_in[16];
    const float* bn3m    = (const float*)d_in[17];
    const float* bn3v    = (const float*)d_in[18];
    const float* w1      = (const float*)d_in[19];
    const float* b1      = (const float*)d_in[20];
    const float* w2      = (const float*)d_in[21];
    const float* b2      = (const float*)d_in[22];
    const float* gate_w  = (const float*)d_in[23];
    const float* gate_b  = (const float*)d_in[24];

    int B = in_sizes[0] / (3 * 32 * 32);
    if (B > 4096) B = 4096;

    conv1_kernel<<<B, 256>>>(x, c1w, c1b, bn1g, bn1b, bn1m, bn1v);
    conv2_kernel<<<B * 8, 128>>>(c2w, c2b, bn2g, bn2b, bn2m, bn2v);
    conv3_kernel<<<B * 16, 128>>>(c3w, c3b, bn3g, bn3b, bn3m, bn3v);
    moe_kernel<<<(B + 7) / 8, 256>>>(w1, b1, w2, b2, gate_w, gate_b, (float*)d_out, B);
}

// round 6
// speedup vs baseline: 1.1353x; 1.1353x over previous
#include <cuda_runtime.h>
#include <math.h>

#define BN_EPS 1e-5f

typedef unsigned long long ull;

__device__ __forceinline__ ull pk2(float lo, float hi) {
    ull r; asm("mov.b64 %0, {%1, %2};" : "=l"(r) : "f"(lo), "f"(hi)); return r;
}
__device__ __forceinline__ float2 upk2(ull v) {
    float2 f; asm("mov.b64 {%0, %1}, %2;" : "=f"(f.x), "=f"(f.y) : "l"(v)); return f;
}
__device__ __forceinline__ ull ff2(ull a, ull b, ull c) {
    ull d; asm("fma.rn.f32x2 %0, %1, %2, %3;" : "=l"(d) : "l"(a), "l"(b), "l"(c)); return d;
}

// ---------------- scratch (device globals; no allocation allowed) ----------------
__device__ float g_h1[4096 * 32 * 16 * 16];   // 128 MB  [B,32,16,16]
__device__ float g_h2[4096 * 64 * 8 * 8];     //  64 MB  [B,64,8,8]
__device__ float g_feat[4096 * 128];          //   2 MB  [B,128]

// =============================================================================
// Stage 1: conv(3->32) + BN + ReLU + pool. grid=B, block=128.
// Thread: 2 oc (oc-pair in lane -> input LDS broadcast), 8 conv cols, 2 conv
// rows packed f32x2. 8 reps x 8 slots cover 16 pooled rows x 4 col quarters.
// =============================================================================
__global__ __launch_bounds__(128) void conv1_kernel(
    const float* __restrict__ x,
    const float* __restrict__ w,     // [32,3,3,3]
    const float* __restrict__ bias,
    const float* __restrict__ gam,
    const float* __restrict__ bet,
    const float* __restrict__ mean,
    const float* __restrict__ var)
{
    __shared__ float s_in[3][34][36];   // zero-padded rows+cols
    __shared__ float s_w[32 * 27];
    __shared__ float s_scale[32], s_shift[32];
    __shared__ float s_stg[32][34];     // staging: 32 oc x (2 rows x 16 cols)

    const int b = blockIdx.x;
    const int tid = threadIdx.x;
    const float* xb = x + (size_t)b * 3 * 32 * 32;

    for (int i = tid; i < 3 * 34 * 36; i += 128) {
        int c = i % 36;
        int r = (i / 36) % 34;
        int ch = i / (36 * 34);
        float v = 0.f;
        if (r >= 1 && r <= 32 && c >= 1 && c <= 32)
            v = xb[ch * 1024 + (r - 1) * 32 + (c - 1)];
        s_in[ch][r][c] = v;
    }
    for (int i = tid; i < 32 * 27; i += 128) s_w[i] = w[i];
    if (tid < 32) {
        float inv = gam[tid] * rsqrtf(var[tid] + BN_EPS);
        s_scale[tid] = inv;
        s_shift[tid] = (bias[tid] - mean[tid]) * inv + bet[tid];
    }
    __syncthreads();

    const int ocp = tid & 15;
    const int oc0 = ocp * 2;
    const int slot = tid >> 4;          // 0..7
    float* ob = g_h1 + (size_t)b * 8192;

    for (int rep = 0; rep < 8; rep++) {
        int combo = rep * 8 + slot;     // 0..63
        int py = combo >> 2;            // pooled row 0..15
        int q = combo & 3;              // col quarter
        int r0 = 2 * py;                // padded row base (4 rows used)
        int x0 = q * 8;                 // padded col base

        ull acc[2][8];
        #pragma unroll
        for (int i = 0; i < 8; i++) { acc[0][i] = 0ull; acc[1][i] = 0ull; }

        #pragma unroll
        for (int ic = 0; ic < 3; ic++) {
            const float* wq0 = &s_w[oc0 * 27 + ic * 9];
            const float* wq1 = wq0 + 27;
            ull wp0[9], wp1[9];
            #pragma unroll
            for (int k = 0; k < 9; k++) {
                float a = wq0[k], c_ = wq1[k];
                wp0[k] = pk2(a, a);
                wp1[k] = pk2(c_, c_);
            }
            float v0, v1, v2, v3;
            v0 = s_in[ic][r0][x0];     v1 = s_in[ic][r0 + 1][x0];
            v2 = s_in[ic][r0 + 2][x0]; v3 = s_in[ic][r0 + 3][x0];
            ull X0 = pk2(v0, v1), Y0 = pk2(v1, v2), Z0 = pk2(v2, v3);
            v0 = s_in[ic][r0][x0 + 1];     v1 = s_in[ic][r0 + 1][x0 + 1];
            v2 = s_in[ic][r0 + 2][x0 + 1]; v3 = s_in[ic][r0 + 3][x0 + 1];
            ull X1 = pk2(v0, v1), Y1 = pk2(v1, v2), Z1 = pk2(v2, v3);

            #pragma unroll
            for (int cx = 0; cx < 8; cx++) {
                int c = x0 + cx + 2;
                v0 = s_in[ic][r0][c];     v1 = s_in[ic][r0 + 1][c];
                v2 = s_in[ic][r0 + 2][c]; v3 = s_in[ic][r0 + 3][c];
                ull X2 = pk2(v0, v1), Y2 = pk2(v1, v2), Z2 = pk2(v2, v3);
                ull t = acc[0][cx];
                t = ff2(wp0[0], X0, t); t = ff2(wp0[1], X1, t); t = ff2(wp0[2], X2, t);
                t = ff2(wp0[3], Y0, t); t = ff2(wp0[4], Y1, t); t = ff2(wp0[5], Y2, t);
                t = ff2(wp0[6], Z0, t); t = ff2(wp0[7], Z1, t); t = ff2(wp0[8], Z2, t);
                acc[0][cx] = t;
                ull u = acc[1][cx];
                u = ff2(wp1[0], X0, u); u = ff2(wp1[1], X1, u); u = ff2(wp1[2], X2, u);
                u = ff2(wp1[3], Y0, u); u = ff2(wp1[4], Y1, u); u = ff2(wp1[5], Y2, u);
                u = ff2(wp1[6], Z0, u); u = ff2(wp1[7], Z1, u); u = ff2(wp1[8], Z2, u);
                acc[1][cx] = u;
                X0 = X1; X1 = X2; Y0 = Y1; Y1 = Y2; Z0 = Z1; Z1 = Z2;
            }
        }

        __syncthreads();   // previous rep's coop store done -> safe to overwrite s_stg
        #pragma unroll
        for (int k = 0; k < 2; k++) {
            int oc = oc0 + k;
            float sc = s_scale[oc], sh = s_shift[oc];
            #pragma unroll
            for (int px = 0; px < 4; px++) {
                float2 pa = upk2(acc[k][2 * px]);
                float2 pb = upk2(acc[k][2 * px + 1]);
                float v00 = fmaxf(fmaf(pa.x, sc, sh), 0.f);
                float v10 = fmaxf(fmaf(pa.y, sc, sh), 0.f);
                float v01 = fmaxf(fmaf(pb.x, sc, sh), 0.f);
                float v11 = fmaxf(fmaf(pb.y, sc, sh), 0.f);
                s_stg[oc][(py & 1) * 16 + q * 4 + px] =
                    fmaxf(fmaxf(v00, v01), fmaxf(v10, v11));
            }
        }
        __syncthreads();
        // coalesced store of this rep's 2 pooled rows for all 32 oc
        for (int i = tid; i < 1024; i += 128) {
            int oc = i >> 5, pos = i & 31;
            ob[oc * 256 + (rep * 2 + (pos >> 4)) * 16 + (pos & 15)] = s_stg[oc][pos];
        }
    }
}

// =============================================================================
// Stage 2: conv(32->64) + BN + ReLU + pool. grid=B*8, block=64.
// Thread: 2 oc x 1 pooled row (packed f32x2 row pair) x 4 pooled cols (half).
// Row-edge masks folded into packed weights. Input smem row stride 18
// (conflict-free across the 16 (py,half) lanes), weight stride 289.
// =============================================================================
__global__ __launch_bounds__(64) void conv2_kernel(
    const float* __restrict__ w,     // [64,32,3,3]
    const float* __restrict__ bias,
    const float* __restrict__ gam,
    const float* __restrict__ bet,
    const float* __restrict__ mean,
    const float* __restrict__ var)
{
    __shared__ float s_in[32 * 288];   // ic stride 288 = 16 rows x 18 cols
    __shared__ float s_w[8 * 289];

    const int b = blockIdx.x >> 3;
    const int oc_base = (blockIdx.x & 7) * 8;
    const int tid = threadIdx.x;
    const float* ib = g_h1 + (size_t)b * 8192;

    for (int i = tid; i < 9216; i += 64) {
        int c = i % 18;
        int r = (i / 18) % 16;
        int ic = i / 288;
        float v = 0.f;
        if (c >= 1 && c <= 16) v = ib[ic * 256 + r * 16 + (c - 1)];
        s_in[ic * 288 + r * 18 + c] = v;
    }
    for (int i = tid; i < 2304; i += 64) {
        int oc = i / 288, j = i % 288;
        s_w[oc * 289 + j] = w[(oc_base + oc) * 288 + j];
    }
    __syncthreads();

    const int ocp = tid >> 4;           // 0..3
    const int oc0 = ocp * 2;
    const int py = (tid >> 1) & 7;
    const int half = tid & 1;
    const int x0 = half * 8;            // padded col base (cols x0..x0+9)
    const float m0 = (py > 0) ? 1.f : 0.f;
    const float m3 = (py < 7) ? 1.f : 0.f;
    const int rm1 = (py > 0) ? 2 * py - 1 : 0;
    const int r_0 = 2 * py, r_1 = 2 * py + 1;
    const int r_2 = (py < 7) ? 2 * py + 2 : 15;

    ull acc[2][8];
    #pragma unroll
    for (int i = 0; i < 8; i++) { acc[0][i] = 0ull; acc[1][i] = 0ull; }

    for (int ic = 0; ic < 32; ic++) {
        const float* wq = &s_w[oc0 * 289 + ic * 9];
        ull wp0[9], wp1[9];
        #pragma unroll
        for (int k = 0; k < 3; k++) {
            wp0[k]     = pk2(m0 * wq[k], wq[k]);
            wp0[3 + k] = pk2(wq[3 + k], wq[3 + k]);
            wp0[6 + k] = pk2(wq[6 + k], m3 * wq[6 + k]);
            wp1[k]     = pk2(m0 * wq[289 + k], wq[289 + k]);
            wp1[3 + k] = pk2(wq[289 + 3 + k], wq[289 + 3 + k]);
            wp1[6 + k] = pk2(wq[289 + 6 + k], m3 * wq[289 + 6 + k]);
        }
        const float* icb = &s_in[ic * 288];
        float a, b0, c0, d;
        a = icb[rm1 * 18 + x0]; b0 = icb[r_0 * 18 + x0];
        c0 = icb[r_1 * 18 + x0]; d = icb[r_2 * 18 + x0];
        ull X0 = pk2(a, b0), Y0 = pk2(b0, c0), Z0 = pk2(c0, d);
        a = icb[rm1 * 18 + x0 + 1]; b0 = icb[r_0 * 18 + x0 + 1];
        c0 = icb[r_1 * 18 + x0 + 1]; d = icb[r_2 * 18 + x0 + 1];
        ull X1 = pk2(a, b0), Y1 = pk2(b0, c0), Z1 = pk2(c0, d);

        #pragma unroll
        for (int cx = 0; cx < 8; cx++) {
            int c = x0 + cx + 2;
            a = icb[rm1 * 18 + c]; b0 = icb[r_0 * 18 + c];
            c0 = icb[r_1 * 18 + c]; d = icb[r_2 * 18 + c];
            ull X2 = pk2(a, b0), Y2 = pk2(b0, c0), Z2 = pk2(c0, d);
            ull t = acc[0][cx];
            t = ff2(wp0[0], X0, t); t = ff2(wp0[1], X1, t); t = ff2(wp0[2], X2, t);
            t = ff2(wp0[3], Y0, t); t = ff2(wp0[4], Y1, t); t = ff2(wp0[5], Y2, t);
            t = ff2(wp0[6], Z0, t); t = ff2(wp0[7], Z1, t); t = ff2(wp0[8], Z2, t);
            acc[0][cx] = t;
            ull u = acc[1][cx];
            u = ff2(wp1[0], X0, u); u = ff2(wp1[1], X1, u); u = ff2(wp1[2], X2, u);
            u = ff2(wp1[3], Y0, u); u = ff2(wp1[4], Y1, u); u = ff2(wp1[5], Y2, u);
            u = ff2(wp1[6], Z0, u); u = ff2(wp1[7], Z1, u); u = ff2(wp1[8], Z2, u);
            acc[1][cx] = u;
            X0 = X1; X1 = X2; Y0 = Y1; Y1 = Y2; Z0 = Z1; Z1 = Z2;
        }
    }

    #pragma unroll
    for (int k = 0; k < 2; k++) {
        const int oc = oc_base + oc0 + k;
        float inv = gam[oc] * rsqrtf(var[oc] + BN_EPS);
        float sh = (bias[oc] - mean[oc]) * inv + bet[oc];
        float4 o;
        float* po = &o.x;
        #pragma unroll
        for (int px = 0; px < 4; px++) {
            float2 pa = upk2(acc[k][2 * px]);
            float2 pb = upk2(acc[k][2 * px + 1]);
            float v00 = fmaxf(fmaf(pa.x, inv, sh), 0.f);
            float v10 = fmaxf(fmaf(pa.y, inv, sh), 0.f);
            float v01 = fmaxf(fmaf(pb.x, inv, sh), 0.f);
            float v11 = fmaxf(fmaf(pb.y, inv, sh), 0.f);
            po[px] = fmaxf(fmaxf(v00, v01), fmaxf(v10, v11));
        }
        *(float4*)(g_h2 + (size_t)b * 4096 + (size_t)oc * 64 + py * 8 + half * 4) = o;
    }
}

// =============================================================================
// Stage 3: conv(64->128) + BN + ReLU + pool + global avgpool. grid=B*16,
// block=128 = icq(8) x ocp(4, 2 oc each) x py(4). Weight smem union-reused
// for the cross-icq partial reduction.
// =============================================================================
__global__ __launch_bounds__(128) void conv3_kernel(
    const float* __restrict__ w,     // [128,64,3,3]
    const float* __restrict__ bias,
    const float* __restrict__ gam,
    const float* __restrict__ bet,
    const float* __restrict__ mean,
    const float* __restrict__ var)
{
    __shared__ float s_in[64 * 82];          // ic stride 82 = 8 rows x 10 cols (+2 pad)
    __shared__ union { float w[8 * 577]; float part[4616]; } su;
    __shared__ float s_red[8][17];

    const int b = blockIdx.x >> 4;
    const int oc_base = (blockIdx.x & 15) * 8;
    const int tid = threadIdx.x;
    const float* ib = g_h2 + (size_t)b * 4096;

    for (int i = tid; i < 5120; i += 128) {
        int c = i % 10;
        int r = (i / 10) % 8;
        int ic = i / 80;
        float v = 0.f;
        if (c >= 1 && c <= 8) v = ib[ic * 64 + r * 8 + (c - 1)];
        s_in[ic * 82 + r * 10 + c] = v;
    }
    for (int i = tid; i < 4608; i += 128) {
        int oc = i / 576, j = i % 576;
        su.w[oc * 577 + j] = w[(oc_base + oc) * 576 + j];
    }

    // prefetch BN params for the reduction role (hide LDG behind mainloop)
    const int red_oc = oc_base + (tid >> 4);
    float pg = gam[red_oc], pv = var[red_oc], pb = bias[red_oc];
    float pm = mean[red_oc], pbe = bet[red_oc];
    __syncthreads();

    const int icq = tid >> 4;               // 0..7
    const int ocp = (tid >> 2) & 3;
    const int py = tid & 3;
    const int oc0 = ocp * 2;
    const float m0 = (py > 0) ? 1.f : 0.f;
    const float m3 = (py < 3) ? 1.f : 0.f;
    const int rm1 = (py > 0) ? 2 * py - 1 : 0;
    const int r_0 = 2 * py, r_1 = 2 * py + 1;
    const int r_2 = (py < 3) ? 2 * py + 2 : 7;

    ull acc[2][8];
    #pragma unroll
    for (int i = 0; i < 8; i++) { acc[0][i] = 0ull; acc[1][i] = 0ull; }

    for (int ici = 0; ici < 8; ici++) {
        int ic = icq * 8 + ici;
        const float* wq = &su.w[oc0 * 577 + ic * 9];
        ull wp0[9], wp1[9];
        #pragma unroll
        for (int k = 0; k < 3; k++) {
            wp0[k]     = pk2(m0 * wq[k], wq[k]);
            wp0[3 + k] = pk2(wq[3 + k], wq[3 + k]);
            wp0[6 + k] = pk2(wq[6 + k], m3 * wq[6 + k]);
            wp1[k]     = pk2(m0 * wq[577 + k], wq[577 + k]);
            wp1[3 + k] = pk2(wq[577 + 3 + k], wq[577 + 3 + k]);
            wp1[6 + k] = pk2(wq[577 + 6 + k], m3 * wq[577 + 6 + k]);
        }
        const float* icb = &s_in[ic * 82];
        float a, b0, c0, d;
        a = icb[rm1 * 10]; b0 = icb[r_0 * 10]; c0 = icb[r_1 * 10]; d = icb[r_2 * 10];
        ull X0 = pk2(a, b0), Y0 = pk2(b0, c0), Z0 = pk2(c0, d);
        a = icb[rm1 * 10 + 1]; b0 = icb[r_0 * 10 + 1]; c0 = icb[r_1 * 10 + 1]; d = icb[r_2 * 10 + 1];
        ull X1 = pk2(a, b0), Y1 = pk2(b0, c0), Z1 = pk2(c0, d);

        #pragma unroll
        for (int cx = 0; cx < 8; cx++) {
            int c = cx + 2;
            a = icb[rm1 * 10 + c]; b0 = icb[r_0 * 10 + c];
            c0 = icb[r_1 * 10 + c]; d = icb[r_2 * 10 + c];
            ull X2 = pk2(a, b0), Y2 = pk2(b0, c0), Z2 = pk2(c0, d);
            ull t = acc[0][cx];
            t = ff2(wp0[0], X0, t); t = ff2(wp0[1], X1, t); t = ff2(wp0[2], X2, t);
            t = ff2(wp0[3], Y0, t); t = ff2(wp0[4], Y1, t); t = ff2(wp0[5], Y2, t);
            t = ff2(wp0[6], Z0, t); t = ff2(wp0[7], Z1, t); t = ff2(wp0[8], Z2, t);
            acc[0][cx] = t;
            ull u = acc[1][cx];
            u = ff2(wp1[0], X0, u); u = ff2(wp1[1], X1, u); u = ff2(wp1[2], X2, u);
            u = ff2(wp1[3], Y0, u); u = ff2(wp1[4], Y1, u); u = ff2(wp1[5], Y2, u);
            u = ff2(wp1[6], Z0, u); u = ff2(wp1[7], Z1, u); u = ff2(wp1[8], Z2, u);
            acc[1][cx] = u;
            X0 = X1; X1 = X2; Y0 = Y1; Y1 = Y2; Z0 = Z1; Z1 = Z2;
        }
    }

    __syncthreads();   // all weight reads done; union becomes 'part'
    #pragma unroll
    for (int k = 0; k < 2; k++) {
        int base = icq * 545 + (oc0 + k) * 68 + py * 17;
        #pragma unroll
        for (int cx = 0; cx < 8; cx++) {
            float2 p = upk2(acc[k][cx]);
            su.part[base + cx] = p.x;
            su.part[base + 8 + cx] = p.y;
        }
    }
    __syncthreads();

    // reduction over icq + BN + ReLU + 2x2 pool : thread = (oc, py, pooled col g)
    {
        const int roc = tid >> 4, rpy = (tid >> 2) & 3, g = tid & 3;
        float s00 = 0.f, s01 = 0.f, s10 = 0.f, s11 = 0.f;
        #pragma unroll
        for (int q = 0; q < 8; q++) {
            const float* p = &su.part[q * 545 + roc * 68 + rpy * 17];
            s00 += p[2 * g]; s01 += p[2 * g + 1];
            s10 += p[8 + 2 * g]; s11 += p[8 + 2 * g + 1];
        }
        float inv = pg * rsqrtf(pv + BN_EPS);
        float sh = (pb - pm) * inv + pbe;
        float v00 = fmaxf(fmaf(s00, inv, sh), 0.f);
        float v01 = fmaxf(fmaf(s01, inv, sh), 0.f);
        float v10 = fmaxf(fmaf(s10, inv, sh), 0.f);
        float v11 = fmaxf(fmaf(s11, inv, sh), 0.f);
        s_red[roc][rpy * 4 + g] = fmaxf(fmaxf(v00, v01), fmaxf(v10, v11));
    }
    __syncthreads();

    if (tid < 8) {
        float s = 0.f;
        #pragma unroll
        for (int i = 0; i < 16; i++) s += s_red[tid][i];
        g_feat[(size_t)b * 128 + oc_base + tid] = s * (1.f / 16.f);
    }
}

// =============================================================================
// Stage 4: gate (top-2 softmax) + top-2 expert MLPs, fused. (unchanged, 55us)
// =============================================================================
__global__ __launch_bounds__(256) void moe_kernel(
    const float* __restrict__ w1,   // [8,128,64]
    const float* __restrict__ b1,   // [8,64]
    const float* __restrict__ w2,   // [8,64,10]
    const float* __restrict__ b2,   // [8,10]
    const float* __restrict__ gw,   // [128,8]
    const float* __restrict__ gb,   // [8]
    float* __restrict__ out, int B)
{
    __shared__ float s_feat[8][128];
    __shared__ float s_h[8][64];
    __shared__ float s_log[8][8];

    const int warp = threadIdx.x >> 5;
    const int lane = threadIdx.x & 31;
    const int s = blockIdx.x * 8 + warp;
    if (s >= B) return;

    for (int i = lane; i < 128; i += 32) s_feat[warp][i] = g_feat[(size_t)s * 128 + i];
    __syncwarp();

    if (lane < 8) {
        float a = gb[lane];
        for (int f = 0; f < 128; f++) a += s_feat[warp][f] * gw[f * 8 + lane];
        s_log[warp][lane] = a;
    }
    __syncwarp();

    float lg[8];
    #pragma unroll
    for (int e = 0; e < 8; e++) lg[e] = s_log[warp][e];
    int i0 = 0; float v0 = lg[0];
    #pragma unroll
    for (int e = 1; e < 8; e++) if (lg[e] > v0) { v0 = lg[e]; i0 = e; }
    int i1 = -1; float v1 = -3.402823466e38f;
    #pragma unroll
    for (int e = 0; e < 8; e++) if (e != i0 && lg[e] > v1) { v1 = lg[e]; i1 = e; }
    float e1 = expf(v1 - v0);
    float invs = 1.f / (1.f + e1);
    float wts[2] = { invs, e1 * invs };
    int eidx[2] = { i0, i1 };

    float outk = 0.f;
    for (int t = 0; t < 2; t++) {
        const int e = eidx[t];
        const float* w1e = w1 + (size_t)e * 128 * 64;
        float h0 = b1[e * 64 + lane];
        float h1v = b1[e * 64 + lane + 32];
        for (int f = 0; f < 128; f++) {
            float fv = s_feat[warp][f];
            h0  += fv * w1e[f * 64 + lane];
            h1v += fv * w1e[f * 64 + lane + 32];
        }
        s_h[warp][lane] = fmaxf(h0, 0.f);
        s_h[warp][lane + 32] = fmaxf(h1v, 0.f);
        __syncwarp();
        if (lane < 10) {
            const float* w2e = w2 + e * 640;
            float o = b2[e * 10 + lane];
            for (int j = 0; j < 64; j++) o += s_h[warp][j] * w2e[j * 10 + lane];
            outk += wts[t] * o;
        }
        __syncwarp();
    }
    if (lane < 10) out[(size_t)s * 10 + lane] = outk;
}

// =============================================================================
extern "C" void kernel_launch(void* const* d_in, const int* in_sizes, int n_in,
                              void* d_out, int out_size)
{
    const float* x       = (const float*)d_in[0];
    const float* c1w     = (const float*)d_in[1];
    const float* c1b     = (const float*)d_in[2];
    const float* bn1g    = (const float*)d_in[3];
    const float* bn1b    = (const float*)d_in[4];
    const float* bn1m    = (const float*)d_in[5];
    const float* bn1v    = (const float*)d_in[6];
    const float* c2w     = (const float*)d_in[7];
    const float* c2b     = (const float*)d_in[8];
    const float* bn2g    = (const float*)d_in[9];
    const float* bn2b    = (const float*)d_in[10];
    const float* bn2m    = (const float*)d_in[11];
    const float* bn2v    = (const float*)d_in[12];
    const float* c3w     = (const float*)d_in[13];
    const float* c3b     = (const float*)d_in[14];
    const float* bn3g    = (const float*)d_in[15];
    const float* bn3b    = (const float*)d_in[16];
    const float* bn3m    = (const float*)d_in[17];
    const float* bn3v    = (const float*)d_in[18];
    const float* w1      = (const float*)d_in[19];
    const float* b1      = (const float*)d_in[20];
    const float* w2      = (const float*)d_in[21];
    const float* b2      = (const float*)d_in[22];
    const float* gate_w  = (const float*)d_in[23];
    const float* gate_b  = (const float*)d_in[24];

    int B = in_sizes[0] / (3 * 32 * 32);
    if (B > 4096) B = 4096;

    conv1_kernel<<<B, 128>>>(x, c1w, c1b, bn1g, bn1b, bn1m, bn1v);
    conv2_kernel<<<B * 8, 64>>>(c2w, c2b, bn2g, bn2b, bn2m, bn2v);
    conv3_kernel<<<B * 16, 128>>>(c3w, c3b, bn3g, bn3b, bn3m, bn3v);
    moe_kernel<<<(B + 7) / 8, 256>>>(w1, b1, w2, b2, gate_w, gate_b, (float*)d_out, B);
}

// round 7
// speedup vs baseline: 1.7863x; 1.5735x over previous
#include <cuda_runtime.h>
#include <math.h>

#define BN_EPS 1e-5f

typedef unsigned long long ull;

__device__ __forceinline__ ull pk2(float lo, float hi) {
    ull r; asm("mov.b64 %0, {%1, %2};" : "=l"(r) : "f"(lo), "f"(hi)); return r;
}
__device__ __forceinline__ float2 upk2(ull v) {
    float2 f; asm("mov.b64 {%0, %1}, %2;" : "=f"(f.x), "=f"(f.y) : "l"(v)); return f;
}
__device__ __forceinline__ ull ff2(ull a, ull b, ull c) {
    ull d; asm("fma.rn.f32x2 %0, %1, %2, %3;" : "=l"(d) : "l"(a), "l"(b), "l"(c)); return d;
}

// ---------------- scratch (device globals; no allocation allowed) ----------------
__device__ float g_h1[4096 * 32 * 16 * 16];   // 128 MB  [B,32,16,16]
__device__ float g_h2[4096 * 64 * 8 * 8];     //  64 MB  [B,64,8,8]
__device__ float g_feat[4096 * 128];          //   2 MB  [B,128]

__global__ void dummy_kernel() {}

// =============================================================================
// Stage 1: conv(3->32) + BN + ReLU + pool. grid=B, block=128. (unchanged)
// =============================================================================
__global__ __launch_bounds__(128) void conv1_kernel(
    const float* __restrict__ x,
    const float* __restrict__ w,     // [32,3,3,3]
    const float* __restrict__ bias,
    const float* __restrict__ gam,
    const float* __restrict__ bet,
    const float* __restrict__ mean,
    const float* __restrict__ var)
{
    __shared__ float s_in[3][34][36];
    __shared__ float s_w[32 * 27];
    __shared__ float s_scale[32], s_shift[32];
    __shared__ float s_stg[32][34];

    const int b = blockIdx.x;
    const int tid = threadIdx.x;
    const float* xb = x + (size_t)b * 3 * 32 * 32;

    for (int i = tid; i < 3 * 34 * 36; i += 128) {
        int c = i % 36;
        int r = (i / 36) % 34;
        int ch = i / (36 * 34);
        float v = 0.f;
        if (r >= 1 && r <= 32 && c >= 1 && c <= 32)
            v = xb[ch * 1024 + (r - 1) * 32 + (c - 1)];
        s_in[ch][r][c] = v;
    }
    for (int i = tid; i < 32 * 27; i += 128) s_w[i] = w[i];
    if (tid < 32) {
        float inv = gam[tid] * rsqrtf(var[tid] + BN_EPS);
        s_scale[tid] = inv;
        s_shift[tid] = (bias[tid] - mean[tid]) * inv + bet[tid];
    }
    __syncthreads();

    const int ocp = tid & 15;
    const int oc0 = ocp * 2;
    const int slot = tid >> 4;
    float* ob = g_h1 + (size_t)b * 8192;

    for (int rep = 0; rep < 8; rep++) {
        int combo = rep * 8 + slot;
        int py = combo >> 2;
        int q = combo & 3;
        int r0 = 2 * py;
        int x0 = q * 8;

        ull acc[2][8];
        #pragma unroll
        for (int i = 0; i < 8; i++) { acc[0][i] = 0ull; acc[1][i] = 0ull; }

        #pragma unroll
        for (int ic = 0; ic < 3; ic++) {
            const float* wq0 = &s_w[oc0 * 27 + ic * 9];
            const float* wq1 = wq0 + 27;
            ull wp0[9], wp1[9];
            #pragma unroll
            for (int k = 0; k < 9; k++) {
                float a = wq0[k], c_ = wq1[k];
                wp0[k] = pk2(a, a);
                wp1[k] = pk2(c_, c_);
            }
            float v0, v1, v2, v3;
            v0 = s_in[ic][r0][x0];     v1 = s_in[ic][r0 + 1][x0];
            v2 = s_in[ic][r0 + 2][x0]; v3 = s_in[ic][r0 + 3][x0];
            ull X0 = pk2(v0, v1), Y0 = pk2(v1, v2), Z0 = pk2(v2, v3);
            v0 = s_in[ic][r0][x0 + 1];     v1 = s_in[ic][r0 + 1][x0 + 1];
            v2 = s_in[ic][r0 + 2][x0 + 1]; v3 = s_in[ic][r0 + 3][x0 + 1];
            ull X1 = pk2(v0, v1), Y1 = pk2(v1, v2), Z1 = pk2(v2, v3);

            #pragma unroll
            for (int cx = 0; cx < 8; cx++) {
                int c = x0 + cx + 2;
                v0 = s_in[ic][r0][c];     v1 = s_in[ic][r0 + 1][c];
                v2 = s_in[ic][r0 + 2][c]; v3 = s_in[ic][r0 + 3][c];
                ull X2 = pk2(v0, v1), Y2 = pk2(v1, v2), Z2 = pk2(v2, v3);
                ull t = acc[0][cx];
                t = ff2(wp0[0], X0, t); t = ff2(wp0[1], X1, t); t = ff2(wp0[2], X2, t);
                t = ff2(wp0[3], Y0, t); t = ff2(wp0[4], Y1, t); t = ff2(wp0[5], Y2, t);
                t = ff2(wp0[6], Z0, t); t = ff2(wp0[7], Z1, t); t = ff2(wp0[8], Z2, t);
                acc[0][cx] = t;
                ull u = acc[1][cx];
                u = ff2(wp1[0], X0, u); u = ff2(wp1[1], X1, u); u = ff2(wp1[2], X2, u);
                u = ff2(wp1[3], Y0, u); u = ff2(wp1[4], Y1, u); u = ff2(wp1[5], Y2, u);
                u = ff2(wp1[6], Z0, u); u = ff2(wp1[7], Z1, u); u = ff2(wp1[8], Z2, u);
                acc[1][cx] = u;
                X0 = X1; X1 = X2; Y0 = Y1; Y1 = Y2; Z0 = Z1; Z1 = Z2;
            }
        }

        __syncthreads();
        #pragma unroll
        for (int k = 0; k < 2; k++) {
            int oc = oc0 + k;
            float sc = s_scale[oc], sh = s_shift[oc];
            #pragma unroll
            for (int px = 0; px < 4; px++) {
                float2 pa = upk2(acc[k][2 * px]);
                float2 pb = upk2(acc[k][2 * px + 1]);
                float v00 = fmaxf(fmaf(pa.x, sc, sh), 0.f);
                float v10 = fmaxf(fmaf(pa.y, sc, sh), 0.f);
                float v01 = fmaxf(fmaf(pb.x, sc, sh), 0.f);
                float v11 = fmaxf(fmaf(pb.y, sc, sh), 0.f);
                s_stg[oc][(py & 1) * 16 + q * 4 + px] =
                    fmaxf(fmaxf(v00, v01), fmaxf(v10, v11));
            }
        }
        __syncthreads();
        for (int i = tid; i < 1024; i += 128) {
            int oc = i >> 5, pos = i & 31;
            ob[oc * 256 + (rep * 2 + (pos >> 4)) * 16 + (pos & 15)] = s_stg[oc][pos];
        }
    }
}

// =============================================================================
// Stage 2: conv(32->64) + BN + ReLU + pool. grid=B*4, block=128 (4 warps).
// Lane = oc_l(4) x colpair(8). Column-packed f32x2 accumulators over all 16
// conv rows. Input via contiguous LDS.64 + shfl neighbors (no smem padding,
// no bank conflicts). Two passes of 16 ic through a 16KB input buffer.
// =============================================================================
__global__ __launch_bounds__(128) void conv2_kernel(
    const float* __restrict__ w,     // [64,32,3,3]
    const float* __restrict__ bias,
    const float* __restrict__ gam,
    const float* __restrict__ bet,
    const float* __restrict__ mean,
    const float* __restrict__ var)
{
    __shared__ float s_in[16 * 256];    // 16 ic x 16x16, 16 KB
    __shared__ float s_w[16 * 289];     // 16 oc x 288 (+1 pad), 18.5 KB

    const int b = blockIdx.x >> 2;
    const int oc_base = (blockIdx.x & 3) * 16;
    const int tid = threadIdx.x;
    const int warp = tid >> 5;
    const int lane = tid & 31;
    const int oc_l = lane >> 3;          // 0..3 within warp
    const int cp = lane & 7;             // col pair 0..7
    const int oc_blk = warp * 4 + oc_l;  // 0..15
    const int oc = oc_base + oc_blk;

    // weights for 16 oc (all 32 ic), padded stride 289
    for (int i = tid; i < 16 * 288; i += 128) {
        int o = i / 288, j = i % 288;
        s_w[o * 289 + j] = w[(oc_base + o) * 288 + j];
    }

    // BN params (prefetch; LDG hidden behind weight staging)
    float pg = gam[oc], pv = var[oc], pb = bias[oc], pm = mean[oc], pbe = bet[oc];

    ull acc[16];
    #pragma unroll
    for (int i = 0; i < 16; i++) acc[i] = 0ull;

    for (int pass = 0; pass < 2; pass++) {
        __syncthreads();   // pass0: nothing pending; pass1: all warps done with s_in
        {
            const float4* src = (const float4*)(g_h1 + (size_t)b * 8192 + pass * 4096);
            float4* dst = (float4*)s_in;
            #pragma unroll
            for (int i = 0; i < 8; i++) dst[tid + i * 128] = src[tid + i * 128];
        }
        __syncthreads();

        #pragma unroll 1
        for (int ici = 0; ici < 16; ici++) {
            const int ic = pass * 16 + ici;
            const float* wq = &s_w[oc_blk * 289 + ic * 9];
            ull W[9];
            #pragma unroll
            for (int k = 0; k < 9; k++) { float t = wq[k]; W[k] = pk2(t, t); }

            const float* rowb = &s_in[ici * 256 + 2 * cp];
            #pragma unroll
            for (int r = 0; r < 16; r++) {
                float2 v = *(const float2*)(rowb + r * 16);
                float pl = __shfl_up_sync(0xffffffffu, v.y, 1, 8);
                float nr = __shfl_down_sync(0xffffffffu, v.x, 1, 8);
                if (cp == 0) pl = 0.f;
                if (cp == 7) nr = 0.f;
                ull L = pk2(pl, v.x);
                ull V = pk2(v.x, v.y);
                ull R = pk2(v.y, nr);
                if (r >= 1)
                    acc[r - 1] = ff2(W[6], L, ff2(W[7], V, ff2(W[8], R, acc[r - 1])));
                acc[r] = ff2(W[3], L, ff2(W[4], V, ff2(W[5], R, acc[r])));
                if (r <= 14)
                    acc[r + 1] = ff2(W[0], L, ff2(W[1], V, ff2(W[2], R, acc[r + 1])));
            }
        }
    }

    // BN + ReLU + 2x2 pool: pooled col = cp, pooled rows 0..7
    float inv = pg * rsqrtf(pv + BN_EPS);
    float sh = (pb - pm) * inv + pbe;
    float* ob = g_h2 + (size_t)b * 4096 + (size_t)oc * 64 + cp;
    #pragma unroll
    for (int py = 0; py < 8; py++) {
        float2 a = upk2(acc[2 * py]);
        float2 c = upk2(acc[2 * py + 1]);
        float v00 = fmaxf(fmaf(a.x, inv, sh), 0.f);
        float v01 = fmaxf(fmaf(a.y, inv, sh), 0.f);
        float v10 = fmaxf(fmaf(c.x, inv, sh), 0.f);
        float v11 = fmaxf(fmaf(c.y, inv, sh), 0.f);
        ob[py * 8] = fmaxf(fmaxf(v00, v01), fmaxf(v10, v11));
    }
}

// =============================================================================
// Stage 3: conv(64->128) + BN + ReLU + pool + global avgpool. grid=B*16,
// block=128 (4 warps, each 16 ic of the same 8 oc). Lane = oc_l(8) x cp(4).
// Column-packed accumulators over 8 conv rows; cross-warp ic reduction via
// smem (union with weights).
// =============================================================================
__global__ __launch_bounds__(128) void conv3_kernel(
    const float* __restrict__ w,     // [128,64,3,3]
    const float* __restrict__ bias,
    const float* __restrict__ gam,
    const float* __restrict__ bet,
    const float* __restrict__ mean,
    const float* __restrict__ var)
{
    __shared__ float s_in[64 * 64];                       // 16 KB: ic*64 + r*8 + c
    __shared__ union { float w[8 * 577]; ull part[8 * 96]; } su;   // 18.5 KB

    const int b = blockIdx.x >> 4;
    const int oc_base = (blockIdx.x & 15) * 8;
    const int tid = threadIdx.x;
    const int warp = tid >> 5;
    const int lane = tid & 31;
    const int oc_l = lane >> 2;          // 0..7
    const int cp = lane & 3;             // col pair 0..3
    const int oc = oc_base + oc_l;

    // input 64 ic x 8x8
    {
        const float4* src = (const float4*)(g_h2 + (size_t)b * 4096);
        float4* dst = (float4*)s_in;
        #pragma unroll
        for (int i = 0; i < 8; i++) dst[tid + i * 128] = src[tid + i * 128];
    }
    // weights 8 oc x 576 (+1 pad)
    for (int i = tid; i < 8 * 576; i += 128) {
        int o = i / 576, j = i % 576;
        su.w[o * 577 + j] = w[(oc_base + o) * 576 + j];
    }
    float pg = gam[oc], pv = var[oc], pb = bias[oc], pm = mean[oc], pbe = bet[oc];
    __syncthreads();

    ull acc[8];
    #pragma unroll
    for (int i = 0; i < 8; i++) acc[i] = 0ull;

    #pragma unroll 1
    for (int ici = 0; ici < 16; ici++) {
        const int ic = warp * 16 + ici;
        const float* wq = &su.w[oc_l * 577 + ic * 9];
        ull W[9];
        #pragma unroll
        for (int k = 0; k < 9; k++) { float t = wq[k]; W[k] = pk2(t, t); }

        const float* rowb = &s_in[ic * 64 + 2 * cp];
        #pragma unroll
        for (int r = 0; r < 8; r++) {
            float2 v = *(const float2*)(rowb + r * 8);
            float pl = __shfl_up_sync(0xffffffffu, v.y, 1, 4);
            float nr = __shfl_down_sync(0xffffffffu, v.x, 1, 4);
            if (cp == 0) pl = 0.f;
            if (cp == 3) nr = 0.f;
            ull L = pk2(pl, v.x);
            ull V = pk2(v.x, v.y);
            ull R = pk2(v.y, nr);
            if (r >= 1)
                acc[r - 1] = ff2(W[6], L, ff2(W[7], V, ff2(W[8], R, acc[r - 1])));
            acc[r] = ff2(W[3], L, ff2(W[4], V, ff2(W[5], R, acc[r])));
            if (r <= 6)
                acc[r + 1] = ff2(W[0], L, ff2(W[1], V, ff2(W[2], R, acc[r + 1])));
        }
    }

    __syncthreads();   // all warps done reading su.w; union becomes 'part'
    if (warp > 0) {
        #pragma unroll
        for (int j = 0; j < 8; j++)
            su.part[j * 96 + (warp - 1) * 32 + lane] = acc[j];
    }
    __syncthreads();

    if (warp == 0) {
        #pragma unroll
        for (int j = 0; j < 8; j++) {
            float2 s = upk2(acc[j]);
            #pragma unroll
            for (int q = 0; q < 3; q++) {
                float2 p = upk2(su.part[j * 96 + q * 32 + lane]);
                s.x += p.x; s.y += p.y;
            }
            acc[j] = pk2(s.x, s.y);
        }
        float inv = pg * rsqrtf(pv + BN_EPS);
        float sh = (pb - pm) * inv + pbe;
        float sum = 0.f;
        #pragma unroll
        for (int py = 0; py < 4; py++) {
            float2 a = upk2(acc[2 * py]);
            float2 c = upk2(acc[2 * py + 1]);
            float v00 = fmaxf(fmaf(a.x, inv, sh), 0.f);
            float v01 = fmaxf(fmaf(a.y, inv, sh), 0.f);
            float v10 = fmaxf(fmaf(c.x, inv, sh), 0.f);
            float v11 = fmaxf(fmaf(c.y, inv, sh), 0.f);
            sum += fmaxf(fmaxf(v00, v01), fmaxf(v10, v11));
        }
        // sum over 4 pooled cols (cp groups of 4)
        sum += __shfl_down_sync(0xffffffffu, sum, 2, 4);
        sum += __shfl_down_sync(0xffffffffu, sum, 1, 4);
        if (cp == 0)
            g_feat[(size_t)b * 128 + oc] = sum * (1.f / 16.f);
    }
}

// =============================================================================
// Stage 4: gate (top-2 softmax) + top-2 expert MLPs, fused. (unchanged, 55us)
// =============================================================================
__global__ __launch_bounds__(256) void moe_kernel(
    const float* __restrict__ w1,   // [8,128,64]
    const float* __restrict__ b1,   // [8,64]
    const float* __restrict__ w2,   // [8,64,10]
    const float* __restrict__ b2,   // [8,10]
    const float* __restrict__ gw,   // [128,8]
    const float* __restrict__ gb,   // [8]
    float* __restrict__ out, int B)
{
    __shared__ float s_feat[8][128];
    __shared__ float s_h[8][64];
    __shared__ float s_log[8][8];

    const int warp = threadIdx.x >> 5;
    const int lane = threadIdx.x & 31;
    const int s = blockIdx.x * 8 + warp;
    if (s >= B) return;

    for (int i = lane; i < 128; i += 32) s_feat[warp][i] = g_feat[(size_t)s * 128 + i];
    __syncwarp();

    if (lane < 8) {
        float a = gb[lane];
        for (int f = 0; f < 128; f++) a += s_feat[warp][f] * gw[f * 8 + lane];
        s_log[warp][lane] = a;
    }
    __syncwarp();

    float lg[8];
    #pragma unroll
    for (int e = 0; e < 8; e++) lg[e] = s_log[warp][e];
    int i0 = 0; float v0 = lg[0];
    #pragma unroll
    for (int e = 1; e < 8; e++) if (lg[e] > v0) { v0 = lg[e]; i0 = e; }
    int i1 = -1; float v1 = -3.402823466e38f;
    #pragma unroll
    for (int e = 0; e < 8; e++) if (e != i0 && lg[e] > v1) { v1 = lg[e]; i1 = e; }
    float e1 = expf(v1 - v0);
    float invs = 1.f / (1.f + e1);
    float wts[2] = { invs, e1 * invs };
    int eidx[2] = { i0, i1 };

    float outk = 0.f;
    for (int t = 0; t < 2; t++) {
        const int e = eidx[t];
        const float* w1e = w1 + (size_t)e * 128 * 64;
        float h0 = b1[e * 64 + lane];
        float h1v = b1[e * 64 + lane + 32];
        for (int f = 0; f < 128; f++) {
            float fv = s_feat[warp][f];
            h0  += fv * w1e[f * 64 + lane];
            h1v += fv * w1e[f * 64 + lane + 32];
        }
        s_h[warp][lane] = fmaxf(h0, 0.f);
        s_h[warp][lane + 32] = fmaxf(h1v, 0.f);
        __syncwarp();
        if (lane < 10) {
            const float* w2e = w2 + e * 640;
            float o = b2[e * 10 + lane];
            for (int j = 0; j < 64; j++) o += s_h[warp][j] * w2e[j * 10 + lane];
            outk += wts[t] * o;
        }
        __syncwarp();
    }
    if (lane < 10) out[(size_t)s * 10 + lane] = outk;
}

// =============================================================================
extern "C" void kernel_launch(void* const* d_in, const int* in_sizes, int n_in,
                              void* d_out, int out_size)
{
    const float* x       = (const float*)d_in[0];
    const float* c1w     = (const float*)d_in[1];
    const float* c1b     = (const float*)d_in[2];
    const float* bn1g    = (const float*)d_in[3];
    const float* bn1b    = (const float*)d_in[4];
    const float* bn1m    = (const float*)d_in[5];
    const float* bn1v    = (const float*)d_in[6];
    const float* c2w     = (const float*)d_in[7];
    const float* c2b     = (const float*)d_in[8];
    const float* bn2g    = (const float*)d_in[9];
    const float* bn2b    = (const float*)d_in[10];
    const float* bn2m    = (const float*)d_in[11];
    const float* bn2v    = (const float*)d_in[12];
    const float* c3w     = (const float*)d_in[13];
    const float* c3b     = (const float*)d_in[14];
    const float* bn3g    = (const float*)d_in[15];
    const float* bn3b    = (const float*)d_in[16];
    const float* bn3m    = (const float*)d_in[17];
    const float* bn3v    = (const float*)d_in[18];
    const float* w1      = (const float*)d_in[19];
    const float* b1      = (const float*)d_in[20];
    const float* w2      = (const float*)d_in[21];
    const float* b2      = (const float*)d_in[22];
    const float* gate_w  = (const float*)d_in[23];
    const float* gate_b  = (const float*)d_in[24];

    int B = in_sizes[0] / (3 * 32 * 32);
    if (B > 4096) B = 4096;

    // two no-op launches: shift ncu's profiled slot (-s 5) onto conv2
    dummy_kernel<<<1, 32>>>();
    dummy_kernel<<<1, 32>>>();

    conv1_kernel<<<B, 128>>>(x, c1w, c1b, bn1g, bn1b, bn1m, bn1v);
    conv2_kernel<<<B * 4, 128>>>(c2w, c2b, bn2g, bn2b, bn2m, bn2v);
    conv3_kernel<<<B * 16, 128>>>(c3w, c3b, bn3g, bn3b, bn3m, bn3v);
    moe_kernel<<<(B + 7) / 8, 256>>>(w1, b1, w2, b2, gate_w, gate_b, (float*)d_out, B);
}

// round 8
// speedup vs baseline: 2.0168x; 1.1291x over previous
#include <cuda_runtime.h>
#include <math.h>

#define BN_EPS 1e-5f

typedef unsigned long long ull;

__device__ __forceinline__ ull pk2(float lo, float hi) {
    ull r; asm("mov.b64 %0, {%1, %2};" : "=l"(r) : "f"(lo), "f"(hi)); return r;
}
__device__ __forceinline__ float2 upk2(ull v) {
    float2 f; asm("mov.b64 {%0, %1}, %2;" : "=f"(f.x), "=f"(f.y) : "l"(v)); return f;
}
__device__ __forceinline__ ull ff2(ull a, ull b, ull c) {
    ull d; asm("fma.rn.f32x2 %0, %1, %2, %3;" : "=l"(d) : "l"(a), "l"(b), "l"(c)); return d;
}

// ---------------- scratch (device globals; no allocation allowed) ----------------
__device__ float g_h1[4096 * 32 * 16 * 16];   // 128 MB  [B,32,16,16]
__device__ float g_h2[4096 * 64 * 8 * 8];     //  64 MB  [B,64,8,8]
__device__ float g_feat[4096 * 128];          //   2 MB  [B,128]

__global__ void dummy_kernel() {}

// =============================================================================
// Stage 1: conv(3->32) + BN + ReLU + pool. grid=B, block=128. (unchanged)
// =============================================================================
__global__ __launch_bounds__(128) void conv1_kernel(
    const float* __restrict__ x,
    const float* __restrict__ w,     // [32,3,3,3]
    const float* __restrict__ bias,
    const float* __restrict__ gam,
    const float* __restrict__ bet,
    const float* __restrict__ mean,
    const float* __restrict__ var)
{
    __shared__ float s_in[3][34][36];
    __shared__ float s_w[32 * 27];
    __shared__ float s_scale[32], s_shift[32];
    __shared__ float s_stg[32][34];

    const int b = blockIdx.x;
    const int tid = threadIdx.x;
    const float* xb = x + (size_t)b * 3 * 32 * 32;

    for (int i = tid; i < 3 * 34 * 36; i += 128) {
        int c = i % 36;
        int r = (i / 36) % 34;
        int ch = i / (36 * 34);
        float v = 0.f;
        if (r >= 1 && r <= 32 && c >= 1 && c <= 32)
            v = xb[ch * 1024 + (r - 1) * 32 + (c - 1)];
        s_in[ch][r][c] = v;
    }
    for (int i = tid; i < 32 * 27; i += 128) s_w[i] = w[i];
    if (tid < 32) {
        float inv = gam[tid] * rsqrtf(var[tid] + BN_EPS);
        s_scale[tid] = inv;
        s_shift[tid] = (bias[tid] - mean[tid]) * inv + bet[tid];
    }
    __syncthreads();

    const int ocp = tid & 15;
    const int oc0 = ocp * 2;
    const int slot = tid >> 4;
    float* ob = g_h1 + (size_t)b * 8192;

    for (int rep = 0; rep < 8; rep++) {
        int combo = rep * 8 + slot;
        int py = combo >> 2;
        int q = combo & 3;
        int r0 = 2 * py;
        int x0 = q * 8;

        ull acc[2][8];
        #pragma unroll
        for (int i = 0; i < 8; i++) { acc[0][i] = 0ull; acc[1][i] = 0ull; }

        #pragma unroll
        for (int ic = 0; ic < 3; ic++) {
            const float* wq0 = &s_w[oc0 * 27 + ic * 9];
            const float* wq1 = wq0 + 27;
            ull wp0[9], wp1[9];
            #pragma unroll
            for (int k = 0; k < 9; k++) {
                float a = wq0[k], c_ = wq1[k];
                wp0[k] = pk2(a, a);
                wp1[k] = pk2(c_, c_);
            }
            float v0, v1, v2, v3;
            v0 = s_in[ic][r0][x0];     v1 = s_in[ic][r0 + 1][x0];
            v2 = s_in[ic][r0 + 2][x0]; v3 = s_in[ic][r0 + 3][x0];
            ull X0 = pk2(v0, v1), Y0 = pk2(v1, v2), Z0 = pk2(v2, v3);
            v0 = s_in[ic][r0][x0 + 1];     v1 = s_in[ic][r0 + 1][x0 + 1];
            v2 = s_in[ic][r0 + 2][x0 + 1]; v3 = s_in[ic][r0 + 3][x0 + 1];
            ull X1 = pk2(v0, v1), Y1 = pk2(v1, v2), Z1 = pk2(v2, v3);

            #pragma unroll
            for (int cx = 0; cx < 8; cx++) {
                int c = x0 + cx + 2;
                v0 = s_in[ic][r0][c];     v1 = s_in[ic][r0 + 1][c];
                v2 = s_in[ic][r0 + 2][c]; v3 = s_in[ic][r0 + 3][c];
                ull X2 = pk2(v0, v1), Y2 = pk2(v1, v2), Z2 = pk2(v2, v3);
                ull t = acc[0][cx];
                t = ff2(wp0[0], X0, t); t = ff2(wp0[1], X1, t); t = ff2(wp0[2], X2, t);
                t = ff2(wp0[3], Y0, t); t = ff2(wp0[4], Y1, t); t = ff2(wp0[5], Y2, t);
                t = ff2(wp0[6], Z0, t); t = ff2(wp0[7], Z1, t); t = ff2(wp0[8], Z2, t);
                acc[0][cx] = t;
                ull u = acc[1][cx];
                u = ff2(wp1[0], X0, u); u = ff2(wp1[1], X1, u); u = ff2(wp1[2], X2, u);
                u = ff2(wp1[3], Y0, u); u = ff2(wp1[4], Y1, u); u = ff2(wp1[5], Y2, u);
                u = ff2(wp1[6], Z0, u); u = ff2(wp1[7], Z1, u); u = ff2(wp1[8], Z2, u);
                acc[1][cx] = u;
                X0 = X1; X1 = X2; Y0 = Y1; Y1 = Y2; Z0 = Z1; Z1 = Z2;
            }
        }

        __syncthreads();
        #pragma unroll
        for (int k = 0; k < 2; k++) {
            int oc = oc0 + k;
            float sc = s_scale[oc], sh = s_shift[oc];
            #pragma unroll
            for (int px = 0; px < 4; px++) {
                float2 pa = upk2(acc[k][2 * px]);
                float2 pb = upk2(acc[k][2 * px + 1]);
                float v00 = fmaxf(fmaf(pa.x, sc, sh), 0.f);
                float v10 = fmaxf(fmaf(pa.y, sc, sh), 0.f);
                float v01 = fmaxf(fmaf(pb.x, sc, sh), 0.f);
                float v11 = fmaxf(fmaf(pb.y, sc, sh), 0.f);
                s_stg[oc][(py & 1) * 16 + q * 4 + px] =
                    fmaxf(fmaxf(v00, v01), fmaxf(v10, v11));
            }
        }
        __syncthreads();
        for (int i = tid; i < 1024; i += 128) {
            int oc = i >> 5, pos = i & 31;
            ob[oc * 256 + (rep * 2 + (pos >> 4)) * 16 + (pos & 15)] = s_stg[oc][pos];
        }
    }
}

// =============================================================================
// Stage 2: conv(32->64) + BN + ReLU + pool. grid=B*4, block=128 (4 warps).
// Lane = oc_l(4) x colpair(8). Rows stored zero-bordered [0,v0..v15,0]
// (18 floats, 8B-aligned) so L/R packs are aligned LDS.64 and V = pk2(L.y,R.x).
// No shfl, no sel. Two passes of 16 ic.
// =============================================================================
__global__ __launch_bounds__(128) void conv2_kernel(
    const float* __restrict__ w,     // [64,32,3,3]
    const float* __restrict__ bias,
    const float* __restrict__ gam,
    const float* __restrict__ bet,
    const float* __restrict__ mean,
    const float* __restrict__ var)
{
    __shared__ float s_in[16 * 288];    // 16 ic x 16 rows x 18 floats, 18 KB
    __shared__ float s_w[16 * 289];     // 16 oc x 288 (+1 pad), 18.5 KB

    const int b = blockIdx.x >> 2;
    const int oc_base = (blockIdx.x & 3) * 16;
    const int tid = threadIdx.x;
    const int warp = tid >> 5;
    const int lane = tid & 31;
    const int oc_l = lane >> 3;          // 0..3 within warp
    const int cp = lane & 7;             // col pair 0..7
    const int oc_blk = warp * 4 + oc_l;  // 0..15
    const int oc = oc_base + oc_blk;

    // weights for 16 oc (all 32 ic), padded stride 289
    for (int i = tid; i < 16 * 288; i += 128) {
        int o = i / 288, j = i % 288;
        s_w[o * 289 + j] = w[(oc_base + o) * 288 + j];
    }
    // zero the row borders once (positions 0 and 17 of each of 16x16 rows)
    for (int i = tid; i < 256; i += 128) {
        int ic = i >> 4, r = i & 15;
        s_in[ic * 288 + r * 18] = 0.f;
        s_in[ic * 288 + r * 18 + 17] = 0.f;
    }

    float pg = gam[oc], pv = var[oc], pb = bias[oc], pm = mean[oc], pbe = bet[oc];

    ull acc[16];
    #pragma unroll
    for (int i = 0; i < 16; i++) acc[i] = 0ull;

    for (int pass = 0; pass < 2; pass++) {
        __syncthreads();   // pass0: border zeros done; pass1: warps done with s_in
        {
            const float4* src = (const float4*)(g_h1 + (size_t)b * 8192 + pass * 4096);
            #pragma unroll
            for (int i = 0; i < 8; i++) {
                int idx4 = tid + i * 128;          // 0..1023 float4s
                float4 v = src[idx4];
                int ic = idx4 >> 6;                // 64 float4 per ic
                int r = (idx4 >> 2) & 15;
                int c4 = (idx4 & 3) * 4;
                float* dst = &s_in[ic * 288 + r * 18 + 1 + c4];
                dst[0] = v.x; dst[1] = v.y; dst[2] = v.z; dst[3] = v.w;
            }
        }
        __syncthreads();

        #pragma unroll 1
        for (int ici = 0; ici < 16; ici++) {
            const int ic = pass * 16 + ici;
            const float* wq = &s_w[oc_blk * 289 + ic * 9];
            ull W[9];
            #pragma unroll
            for (int k = 0; k < 9; k++) { float t = wq[k]; W[k] = pk2(t, t); }

            const float* rowb = &s_in[ici * 288 + 2 * cp];
            #pragma unroll
            for (int r = 0; r < 16; r++) {
                ull L = *(const ull*)(rowb + r * 18);
                ull R = *(const ull*)(rowb + r * 18 + 2);
                float2 Lf = upk2(L);
                float2 Rf = upk2(R);
                ull V = pk2(Lf.y, Rf.x);
                if (r >= 1)
                    acc[r - 1] = ff2(W[6], L, ff2(W[7], V, ff2(W[8], R, acc[r - 1])));
                acc[r] = ff2(W[3], L, ff2(W[4], V, ff2(W[5], R, acc[r])));
                if (r <= 14)
                    acc[r + 1] = ff2(W[0], L, ff2(W[1], V, ff2(W[2], R, acc[r + 1])));
            }
        }
    }

    // BN + ReLU + 2x2 pool: pooled col = cp, pooled rows 0..7
    float inv = pg * rsqrtf(pv + BN_EPS);
    float sh = (pb - pm) * inv + pbe;
    float* ob = g_h2 + (size_t)b * 4096 + (size_t)oc * 64 + cp;
    #pragma unroll
    for (int py = 0; py < 8; py++) {
        float2 a = upk2(acc[2 * py]);
        float2 c = upk2(acc[2 * py + 1]);
        float v00 = fmaxf(fmaf(a.x, inv, sh), 0.f);
        float v01 = fmaxf(fmaf(a.y, inv, sh), 0.f);
        float v10 = fmaxf(fmaf(c.x, inv, sh), 0.f);
        float v11 = fmaxf(fmaf(c.y, inv, sh), 0.f);
        ob[py * 8] = fmaxf(fmaxf(v00, v01), fmaxf(v10, v11));
    }
}

// =============================================================================
// Stage 3: conv(64->128) + BN + ReLU + pool + global avgpool. grid=B*16,
// block=128 (4 warps x 16 ic each of the same 8 oc). Lane = oc_l(8) x cp(4).
// Rows stored zero-bordered [0,v0..v7,0] (10 floats); L/R aligned LDS.64,
// V = pk2(L.y,R.x). Cross-warp ic reduction via smem (union with weights).
// =============================================================================
__global__ __launch_bounds__(128) void conv3_kernel(
    const float* __restrict__ w,     // [128,64,3,3]
    const float* __restrict__ bias,
    const float* __restrict__ gam,
    const float* __restrict__ bet,
    const float* __restrict__ mean,
    const float* __restrict__ var)
{
    __shared__ float s_in[64 * 80];                       // 20 KB: ic*80 + r*10 + 1+c
    __shared__ union { float w[8 * 577]; ull part[8 * 96]; } su;   // 18.5 KB

    const int b = blockIdx.x >> 4;
    const int oc_base = (blockIdx.x & 15) * 8;
    const int tid = threadIdx.x;
    const int warp = tid >> 5;
    const int lane = tid & 31;
    const int oc_l = lane >> 2;          // 0..7
    const int cp = lane & 3;             // col pair 0..3
    const int oc = oc_base + oc_l;

    // zero row borders (64 ic x 8 rows x 2)
    for (int i = tid; i < 512; i += 128) {
        int ic = i >> 3, r = i & 7;
        s_in[ic * 80 + r * 10] = 0.f;
        s_in[ic * 80 + r * 10 + 9] = 0.f;
    }
    // input 64 ic x 8x8 into padded rows
    {
        const float4* src = (const float4*)(g_h2 + (size_t)b * 4096);
        #pragma unroll
        for (int i = 0; i < 8; i++) {
            int idx4 = tid + i * 128;           // 0..1023
            float4 v = src[idx4];
            int ic = idx4 >> 4;                 // 16 float4 per ic
            int r = (idx4 >> 1) & 7;
            int c4 = (idx4 & 1) * 4;
            float* dst = &s_in[ic * 80 + r * 10 + 1 + c4];
            dst[0] = v.x; dst[1] = v.y; dst[2] = v.z; dst[3] = v.w;
        }
    }
    // weights 8 oc x 576 (+1 pad)
    for (int i = tid; i < 8 * 576; i += 128) {
        int o = i / 576, j = i % 576;
        su.w[o * 577 + j] = w[(oc_base + o) * 576 + j];
    }
    float pg = gam[oc], pv = var[oc], pb = bias[oc], pm = mean[oc], pbe = bet[oc];
    __syncthreads();

    ull acc[8];
    #pragma unroll
    for (int i = 0; i < 8; i++) acc[i] = 0ull;

    #pragma unroll 1
    for (int ici = 0; ici < 16; ici++) {
        const int ic = warp * 16 + ici;
        const float* wq = &su.w[oc_l * 577 + ic * 9];
        ull W[9];
        #pragma unroll
        for (int k = 0; k < 9; k++) { float t = wq[k]; W[k] = pk2(t, t); }

        const float* rowb = &s_in[ic * 80 + 2 * cp];
        #pragma unroll
        for (int r = 0; r < 8; r++) {
            ull L = *(const ull*)(rowb + r * 10);
            ull R = *(const ull*)(rowb + r * 10 + 2);
            float2 Lf = upk2(L);
            float2 Rf = upk2(R);
            ull V = pk2(Lf.y, Rf.x);
            if (r >= 1)
                acc[r - 1] = ff2(W[6], L, ff2(W[7], V, ff2(W[8], R, acc[r - 1])));
            acc[r] = ff2(W[3], L, ff2(W[4], V, ff2(W[5], R, acc[r])));
            if (r <= 6)
                acc[r + 1] = ff2(W[0], L, ff2(W[1], V, ff2(W[2], R, acc[r + 1])));
        }
    }

    __syncthreads();   // all warps done reading su.w; union becomes 'part'
    if (warp > 0) {
        #pragma unroll
        for (int j = 0; j < 8; j++)
            su.part[j * 96 + (warp - 1) * 32 + lane] = acc[j];
    }
    __syncthreads();

    if (warp == 0) {
        #pragma unroll
        for (int j = 0; j < 8; j++) {
            float2 s = upk2(acc[j]);
            #pragma unroll
            for (int q = 0; q < 3; q++) {
                float2 p = upk2(su.part[j * 96 + q * 32 + lane]);
                s.x += p.x; s.y += p.y;
            }
            acc[j] = pk2(s.x, s.y);
        }
        float inv = pg * rsqrtf(pv + BN_EPS);
        float sh = (pb - pm) * inv + pbe;
        float sum = 0.f;
        #pragma unroll
        for (int py = 0; py < 4; py++) {
            float2 a = upk2(acc[2 * py]);
            float2 c = upk2(acc[2 * py + 1]);
            float v00 = fmaxf(fmaf(a.x, inv, sh), 0.f);
            float v01 = fmaxf(fmaf(a.y, inv, sh), 0.f);
            float v10 = fmaxf(fmaf(c.x, inv, sh), 0.f);
            float v11 = fmaxf(fmaf(c.y, inv, sh), 0.f);
            sum += fmaxf(fmaxf(v00, v01), fmaxf(v10, v11));
        }
        sum += __shfl_down_sync(0xffffffffu, sum, 2, 4);
        sum += __shfl_down_sync(0xffffffffu, sum, 1, 4);
        if (cp == 0)
            g_feat[(size_t)b * 128 + oc] = sum * (1.f / 16.f);
    }
}

// =============================================================================
// Stage 4: gate (top-2 softmax) + top-2 expert MLPs, fused. (unchanged, 55us)
// =============================================================================
__global__ __launch_bounds__(256) void moe_kernel(
    const float* __restrict__ w1,   // [8,128,64]
    const float* __restrict__ b1,   // [8,64]
    const float* __restrict__ w2,   // [8,64,10]
    const float* __restrict__ b2,   // [8,10]
    const float* __restrict__ gw,   // [128,8]
    const float* __restrict__ gb,   // [8]
    float* __restrict__ out, int B)
{
    __shared__ float s_feat[8][128];
    __shared__ float s_h[8][64];
    __shared__ float s_log[8][8];

    const int warp = threadIdx.x >> 5;
    const int lane = threadIdx.x & 31;
    const int s = blockIdx.x * 8 + warp;
    if (s >= B) return;

    for (int i = lane; i < 128; i += 32) s_feat[warp][i] = g_feat[(size_t)s * 128 + i];
    __syncwarp();

    if (lane < 8) {
        float a = gb[lane];
        for (int f = 0; f < 128; f++) a += s_feat[warp][f] * gw[f * 8 + lane];
        s_log[warp][lane] = a;
    }
    __syncwarp();

    float lg[8];
    #pragma unroll
    for (int e = 0; e < 8; e++) lg[e] = s_log[warp][e];
    int i0 = 0; float v0 = lg[0];
    #pragma unroll
    for (int e = 1; e < 8; e++) if (lg[e] > v0) { v0 = lg[e]; i0 = e; }
    int i1 = -1; float v1 = -3.402823466e38f;
    #pragma unroll
    for (int e = 0; e < 8; e++) if (e != i0 && lg[e] > v1) { v1 = lg[e]; i1 = e; }
    float e1 = expf(v1 - v0);
    float invs = 1.f / (1.f + e1);
    float wts[2] = { invs, e1 * invs };
    int eidx[2] = { i0, i1 };

    float outk = 0.f;
    for (int t = 0; t < 2; t++) {
        const int e = eidx[t];
        const float* w1e = w1 + (size_t)e * 128 * 64;
        float h0 = b1[e * 64 + lane];
        float h1v = b1[e * 64 + lane + 32];
        for (int f = 0; f < 128; f++) {
            float fv = s_feat[warp][f];
            h0  += fv * w1e[f * 64 + lane];
            h1v += fv * w1e[f * 64 + lane + 32];
        }
        s_h[warp][lane] = fmaxf(h0, 0.f);
        s_h[warp][lane + 32] = fmaxf(h1v, 0.f);
        __syncwarp();
        if (lane < 10) {
            const float* w2e = w2 + e * 640;
            float o = b2[e * 10 + lane];
            for (int j = 0; j < 64; j++) o += s_h[warp][j] * w2e[j * 10 + lane];
            outk += wts[t] * o;
        }
        __syncwarp();
    }
    if (lane < 10) out[(size_t)s * 10 + lane] = outk;
}

// =============================================================================
extern "C" void kernel_launch(void* const* d_in, const int* in_sizes, int n_in,
                              void* d_out, int out_size)
{
    const float* x       = (const float*)d_in[0];
    const float* c1w     = (const float*)d_in[1];
    const float* c1b     = (const float*)d_in[2];
    const float* bn1g    = (const float*)d_in[3];
    const float* bn1b    = (const float*)d_in[4];
    const float* bn1m    = (const float*)d_in[5];
    const float* bn1v    = (const float*)d_in[6];
    const float* c2w     = (const float*)d_in[7];
    const float* c2b     = (const float*)d_in[8];
    const float* bn2g    = (const float*)d_in[9];
    const float* bn2b    = (const float*)d_in[10];
    const float* bn2m    = (const float*)d_in[11];
    const float* bn2v    = (const float*)d_in[12];
    const float* c3w     = (const float*)d_in[13];
    const float* c3b     = (const float*)d_in[14];
    const float* bn3g    = (const float*)d_in[15];
    const float* bn3b    = (const float*)d_in[16];
    const float* bn3m    = (const float*)d_in[17];
    const float* bn3v    = (const float*)d_in[18];
    const float* w1      = (const float*)d_in[19];
    const float* b1      = (const float*)d_in[20];
    const float* w2      = (const float*)d_in[21];
    const float* b2      = (const float*)d_in[22];
    const float* gate_w  = (const float*)d_in[23];
    const float* gate_b  = (const float*)d_in[24];

    int B = in_sizes[0] / (3 * 32 * 32);
    if (B > 4096) B = 4096;

    // two no-op launches: keep ncu's profiled slot (-s 5) on conv2
    dummy_kernel<<<1, 32>>>();
    dummy_kernel<<<1, 32>>>();

    conv1_kernel<<<B, 128>>>(x, c1w, c1b, bn1g, bn1b, bn1m, bn1v);
    conv2_kernel<<<B * 4, 128>>>(c2w, c2b, bn2g, bn2b, bn2m, bn2v);
    conv3_kernel<<<B * 16, 128>>>(c3w, c3b, bn3g, bn3b, bn3m, bn3v);
    moe_kernel<<<(B + 7) / 8, 256>>>(w1, b1, w2, b2, gate_w, gate_b, (float*)d_out, B);
}

// round 9
// speedup vs baseline: 2.1060x; 1.0442x over previous
#include <cuda_runtime.h>
#include <math.h>

#define BN_EPS 1e-5f

typedef unsigned long long ull;

__device__ __forceinline__ ull pk2(float lo, float hi) {
    ull r; asm("mov.b64 %0, {%1, %2};" : "=l"(r) : "f"(lo), "f"(hi)); return r;
}
__device__ __forceinline__ float2 upk2(ull v) {
    float2 f; asm("mov.b64 {%0, %1}, %2;" : "=f"(f.x), "=f"(f.y) : "l"(v)); return f;
}
__device__ __forceinline__ ull ff2(ull a, ull b, ull c) {
    ull d; asm("fma.rn.f32x2 %0, %1, %2, %3;" : "=l"(d) : "l"(a), "l"(b), "l"(c)); return d;
}

// ---------------- scratch (device globals; no allocation allowed) ----------------
__device__ float g_h1[4096 * 32 * 16 * 16];   // 128 MB  [B,32,16,16]
__device__ float g_h2[4096 * 64 * 8 * 8];     //  64 MB  [B,64,8,8]
__device__ float g_feat[4096 * 128];          //   2 MB  [B,128]

__global__ void dummy_kernel() {}

// =============================================================================
// Stage 1: conv(3->32) + BN + ReLU + pool. grid=B, block=128. (unchanged)
// =============================================================================
__global__ __launch_bounds__(128) void conv1_kernel(
    const float* __restrict__ x,
    const float* __restrict__ w,     // [32,3,3,3]
    const float* __restrict__ bias,
    const float* __restrict__ gam,
    const float* __restrict__ bet,
    const float* __restrict__ mean,
    const float* __restrict__ var)
{
    __shared__ float s_in[3][34][36];
    __shared__ float s_w[32 * 27];
    __shared__ float s_scale[32], s_shift[32];
    __shared__ float s_stg[32][34];

    const int b = blockIdx.x;
    const int tid = threadIdx.x;
    const float* xb = x + (size_t)b * 3 * 32 * 32;

    for (int i = tid; i < 3 * 34 * 36; i += 128) {
        int c = i % 36;
        int r = (i / 36) % 34;
        int ch = i / (36 * 34);
        float v = 0.f;
        if (r >= 1 && r <= 32 && c >= 1 && c <= 32)
            v = xb[ch * 1024 + (r - 1) * 32 + (c - 1)];
        s_in[ch][r][c] = v;
    }
    for (int i = tid; i < 32 * 27; i += 128) s_w[i] = w[i];
    if (tid < 32) {
        float inv = gam[tid] * rsqrtf(var[tid] + BN_EPS);
        s_scale[tid] = inv;
        s_shift[tid] = (bias[tid] - mean[tid]) * inv + bet[tid];
    }
    __syncthreads();

    const int ocp = tid & 15;
    const int oc0 = ocp * 2;
    const int slot = tid >> 4;
    float* ob = g_h1 + (size_t)b * 8192;

    for (int rep = 0; rep < 8; rep++) {
        int combo = rep * 8 + slot;
        int py = combo >> 2;
        int q = combo & 3;
        int r0 = 2 * py;
        int x0 = q * 8;

        ull acc[2][8];
        #pragma unroll
        for (int i = 0; i < 8; i++) { acc[0][i] = 0ull; acc[1][i] = 0ull; }

        #pragma unroll
        for (int ic = 0; ic < 3; ic++) {
            const float* wq0 = &s_w[oc0 * 27 + ic * 9];
            const float* wq1 = wq0 + 27;
            ull wp0[9], wp1[9];
            #pragma unroll
            for (int k = 0; k < 9; k++) {
                float a = wq0[k], c_ = wq1[k];
                wp0[k] = pk2(a, a);
                wp1[k] = pk2(c_, c_);
            }
            float v0, v1, v2, v3;
            v0 = s_in[ic][r0][x0];     v1 = s_in[ic][r0 + 1][x0];
            v2 = s_in[ic][r0 + 2][x0]; v3 = s_in[ic][r0 + 3][x0];
            ull X0 = pk2(v0, v1), Y0 = pk2(v1, v2), Z0 = pk2(v2, v3);
            v0 = s_in[ic][r0][x0 + 1];     v1 = s_in[ic][r0 + 1][x0 + 1];
            v2 = s_in[ic][r0 + 2][x0 + 1]; v3 = s_in[ic][r0 + 3][x0 + 1];
            ull X1 = pk2(v0, v1), Y1 = pk2(v1, v2), Z1 = pk2(v2, v3);

            #pragma unroll
            for (int cx = 0; cx < 8; cx++) {
                int c = x0 + cx + 2;
                v0 = s_in[ic][r0][c];     v1 = s_in[ic][r0 + 1][c];
                v2 = s_in[ic][r0 + 2][c]; v3 = s_in[ic][r0 + 3][c];
                ull X2 = pk2(v0, v1), Y2 = pk2(v1, v2), Z2 = pk2(v2, v3);
                ull t = acc[0][cx];
                t = ff2(wp0[0], X0, t); t = ff2(wp0[1], X1, t); t = ff2(wp0[2], X2, t);
                t = ff2(wp0[3], Y0, t); t = ff2(wp0[4], Y1, t); t = ff2(wp0[5], Y2, t);
                t = ff2(wp0[6], Z0, t); t = ff2(wp0[7], Z1, t); t = ff2(wp0[8], Z2, t);
                acc[0][cx] = t;
                ull u = acc[1][cx];
                u = ff2(wp1[0], X0, u); u = ff2(wp1[1], X1, u); u = ff2(wp1[2], X2, u);
                u = ff2(wp1[3], Y0, u); u = ff2(wp1[4], Y1, u); u = ff2(wp1[5], Y2, u);
                u = ff2(wp1[6], Z0, u); u = ff2(wp1[7], Z1, u); u = ff2(wp1[8], Z2, u);
                acc[1][cx] = u;
                X0 = X1; X1 = X2; Y0 = Y1; Y1 = Y2; Z0 = Z1; Z1 = Z2;
            }
        }

        __syncthreads();
        #pragma unroll
        for (int k = 0; k < 2; k++) {
            int oc = oc0 + k;
            float sc = s_scale[oc], sh = s_shift[oc];
            #pragma unroll
            for (int px = 0; px < 4; px++) {
                float2 pa = upk2(acc[k][2 * px]);
                float2 pb = upk2(acc[k][2 * px + 1]);
                float v00 = fmaxf(fmaf(pa.x, sc, sh), 0.f);
                float v10 = fmaxf(fmaf(pa.y, sc, sh), 0.f);
                float v01 = fmaxf(fmaf(pb.x, sc, sh), 0.f);
                float v11 = fmaxf(fmaf(pb.y, sc, sh), 0.f);
                s_stg[oc][(py & 1) * 16 + q * 4 + px] =
                    fmaxf(fmaxf(v00, v01), fmaxf(v10, v11));
            }
        }
        __syncthreads();
        for (int i = tid; i < 1024; i += 128) {
            int oc = i >> 5, pos = i & 31;
            ob[oc * 256 + (rep * 2 + (pos >> 4)) * 16 + (pos & 15)] = s_stg[oc][pos];
        }
    }
}

// =============================================================================
// Stage 2: conv(32->64) + BN + ReLU + pool. grid=B*4, block=128 (4 warps).
// Warp w: half h=w>>1 (conv rows 8h..8h+7), oc-set s=w&1. Lane = ocg(4)x cp(8);
// thread owns 2 oc x 2 cols x 8 out-rows (reads 9 in-rows). Input LDS
// amortized over 2 oc -> FMA-bound. Two passes of 16 ic.
// =============================================================================
__global__ __launch_bounds__(128) void conv2_kernel(
    const float* __restrict__ w,     // [64,32,3,3]
    const float* __restrict__ bias,
    const float* __restrict__ gam,
    const float* __restrict__ bet,
    const float* __restrict__ mean,
    const float* __restrict__ var)
{
    __shared__ float s_in[16 * 288];    // 16 ic x 16 rows x 18 floats [0,v..,0]
    __shared__ float s_w[16 * 289];     // 16 oc x 288 (+1 pad)

    const int b = blockIdx.x >> 2;
    const int oc_base = (blockIdx.x & 3) * 16;
    const int tid = threadIdx.x;
    const int warp = tid >> 5;
    const int lane = tid & 31;
    const int cp = lane & 7;             // col pair 0..7
    const int ocg = lane >> 3;           // 0..3
    const int h = warp >> 1;             // row half
    const int st = warp & 1;             // oc set
    const int oc0_blk = st * 8 + ocg * 2;   // 0..14 even
    const int oc0 = oc_base + oc0_blk;

    for (int i = tid; i < 16 * 288; i += 128) {
        int o = i / 288, j = i % 288;
        s_w[o * 289 + j] = w[(oc_base + o) * 288 + j];
    }
    for (int i = tid; i < 256; i += 128) {
        int ic = i >> 4, r = i & 15;
        s_in[ic * 288 + r * 18] = 0.f;
        s_in[ic * 288 + r * 18 + 17] = 0.f;
    }

    ull acc0[8], acc1[8];
    #pragma unroll
    for (int i = 0; i < 8; i++) { acc0[i] = 0ull; acc1[i] = 0ull; }

    for (int pass = 0; pass < 2; pass++) {
        __syncthreads();
        {
            const float4* src = (const float4*)(g_h1 + (size_t)b * 8192 + pass * 4096);
            #pragma unroll
            for (int i = 0; i < 8; i++) {
                int idx4 = tid + i * 128;
                float4 v = src[idx4];
                int ic = idx4 >> 6;
                int r = (idx4 >> 2) & 15;
                int c4 = (idx4 & 3) * 4;
                float* dst = &s_in[ic * 288 + r * 18 + 1 + c4];
                dst[0] = v.x; dst[1] = v.y; dst[2] = v.z; dst[3] = v.w;
            }
        }
        __syncthreads();

        if (h == 0) {
            #pragma unroll 1
            for (int ici = 0; ici < 16; ici++) {
                const float* wq0 = &s_w[oc0_blk * 289 + (pass * 16 + ici) * 9];
                const float* wq1 = wq0 + 289;
                ull W0[9], W1[9];
                #pragma unroll
                for (int k = 0; k < 9; k++) {
                    float a = wq0[k], c_ = wq1[k];
                    W0[k] = pk2(a, a); W1[k] = pk2(c_, c_);
                }
                const float* rowb = &s_in[ici * 288 + 2 * cp];
                #pragma unroll
                for (int r = 0; r < 9; r++) {
                    ull L = *(const ull*)(rowb + r * 18);
                    ull R = *(const ull*)(rowb + r * 18 + 2);
                    float2 Lf = upk2(L), Rf = upk2(R);
                    ull V = pk2(Lf.y, Rf.x);
                    if (r >= 1) {
                        acc0[r - 1] = ff2(W0[6], L, ff2(W0[7], V, ff2(W0[8], R, acc0[r - 1])));
                        acc1[r - 1] = ff2(W1[6], L, ff2(W1[7], V, ff2(W1[8], R, acc1[r - 1])));
                    }
                    if (r <= 7) {
                        acc0[r] = ff2(W0[3], L, ff2(W0[4], V, ff2(W0[5], R, acc0[r])));
                        acc1[r] = ff2(W1[3], L, ff2(W1[4], V, ff2(W1[5], R, acc1[r])));
                    }
                    if (r <= 6) {
                        acc0[r + 1] = ff2(W0[0], L, ff2(W0[1], V, ff2(W0[2], R, acc0[r + 1])));
                        acc1[r + 1] = ff2(W1[0], L, ff2(W1[1], V, ff2(W1[2], R, acc1[r + 1])));
                    }
                }
            }
        } else {
            #pragma unroll 1
            for (int ici = 0; ici < 16; ici++) {
                const float* wq0 = &s_w[oc0_blk * 289 + (pass * 16 + ici) * 9];
                const float* wq1 = wq0 + 289;
                ull W0[9], W1[9];
                #pragma unroll
                for (int k = 0; k < 9; k++) {
                    float a = wq0[k], c_ = wq1[k];
                    W0[k] = pk2(a, a); W1[k] = pk2(c_, c_);
                }
                const float* rowb = &s_in[ici * 288 + 2 * cp];
                #pragma unroll
                for (int ri = 0; ri < 9; ri++) {
                    const int r = 7 + ri;          // global in row
                    const int t = ri - 1;          // local out base
                    ull L = *(const ull*)(rowb + r * 18);
                    ull R = *(const ull*)(rowb + r * 18 + 2);
                    float2 Lf = upk2(L), Rf = upk2(R);
                    ull V = pk2(Lf.y, Rf.x);
                    if (t >= 1) {
                        acc0[t - 1] = ff2(W0[6], L, ff2(W0[7], V, ff2(W0[8], R, acc0[t - 1])));
                        acc1[t - 1] = ff2(W1[6], L, ff2(W1[7], V, ff2(W1[8], R, acc1[t - 1])));
                    }
                    if (t >= 0 && t <= 7) {
                        acc0[t] = ff2(W0[3], L, ff2(W0[4], V, ff2(W0[5], R, acc0[t])));
                        acc1[t] = ff2(W1[3], L, ff2(W1[4], V, ff2(W1[5], R, acc1[t])));
                    }
                    if (t <= 6) {
                        acc0[t + 1] = ff2(W0[0], L, ff2(W0[1], V, ff2(W0[2], R, acc0[t + 1])));
                        acc1[t + 1] = ff2(W1[0], L, ff2(W1[1], V, ff2(W1[2], R, acc1[t + 1])));
                    }
                }
            }
        }
    }

    // BN + ReLU + 2x2 pool; local pooled rows 0..3 -> global h*4+j, col = cp
    #pragma unroll
    for (int k = 0; k < 2; k++) {
        const int oc = oc0 + k;
        const ull* ac = k ? acc1 : acc0;
        float inv = gam[oc] * rsqrtf(var[oc] + BN_EPS);
        float sh = (bias[oc] - mean[oc]) * inv + bet[oc];
        float* ob = g_h2 + (size_t)b * 4096 + (size_t)oc * 64 + cp;
        #pragma unroll
        for (int j = 0; j < 4; j++) {
            float2 a = upk2(ac[2 * j]);
            float2 c = upk2(ac[2 * j + 1]);
            float v00 = fmaxf(fmaf(a.x, inv, sh), 0.f);
            float v01 = fmaxf(fmaf(a.y, inv, sh), 0.f);
            float v10 = fmaxf(fmaf(c.x, inv, sh), 0.f);
            float v11 = fmaxf(fmaf(c.y, inv, sh), 0.f);
            ob[(h * 4 + j) * 8] = fmaxf(fmaxf(v00, v01), fmaxf(v10, v11));
        }
    }
}

// =============================================================================
// Stage 3: conv(64->128) + BN + ReLU + pool + global avgpool. grid=B*2,
// block=128 (4 warps x 16 oc = 64 oc). Lane = ocg(8, 2 oc each) x cp(4);
// thread owns 2 oc x 2 cols x all 8 rows over all 64 ic. Weights staged in
// 8 passes of 8 ic. No cross-warp reduction.
// =============================================================================
__global__ __launch_bounds__(128) void conv3_kernel(
    const float* __restrict__ w,     // [128,64,3,3]
    const float* __restrict__ bias,
    const float* __restrict__ gam,
    const float* __restrict__ bet,
    const float* __restrict__ mean,
    const float* __restrict__ var)
{
    __shared__ float s_in[64 * 80];     // 20 KB: ic*80 + r*10 + 1+c, rows [0,v..,0]
    __shared__ float s_w[64 * 73];      // per pass: 64 oc x (8 ic x 9, +1 pad)

    const int b = blockIdx.x >> 1;
    const int oc_base = (blockIdx.x & 1) * 64;
    const int tid = threadIdx.x;
    const int warp = tid >> 5;
    const int lane = tid & 31;
    const int cp = lane & 3;             // col pair 0..3
    const int ocg = lane >> 2;           // 0..7
    const int oc0_blk = warp * 16 + ocg * 2;   // 0..62 even
    const int oc0 = oc_base + oc0_blk;

    // border zeros
    for (int i = tid; i < 512; i += 128) {
        int ic = i >> 3, r = i & 7;
        s_in[ic * 80 + r * 10] = 0.f;
        s_in[ic * 80 + r * 10 + 9] = 0.f;
    }
    // input 64 ic x 8x8 into padded rows
    {
        const float4* src = (const float4*)(g_h2 + (size_t)b * 4096);
        #pragma unroll
        for (int i = 0; i < 8; i++) {
            int idx4 = tid + i * 128;
            float4 v = src[idx4];
            int ic = idx4 >> 4;
            int r = (idx4 >> 1) & 7;
            int c4 = (idx4 & 1) * 4;
            float* dst = &s_in[ic * 80 + r * 10 + 1 + c4];
            dst[0] = v.x; dst[1] = v.y; dst[2] = v.z; dst[3] = v.w;
        }
    }

    ull acc0[8], acc1[8];
    #pragma unroll
    for (int i = 0; i < 8; i++) { acc0[i] = 0ull; acc1[i] = 0ull; }

    for (int pass = 0; pass < 8; pass++) {
        __syncthreads();   // pass0: input+borders done; else: s_w reads done
        for (int i = tid; i < 4608; i += 128) {
            int o = i / 72, j = i % 72;
            s_w[o * 73 + j] = w[(size_t)(oc_base + o) * 576 + pass * 72 + j];
        }
        __syncthreads();

        #pragma unroll 1
        for (int ici = 0; ici < 8; ici++) {
            const int ic = pass * 8 + ici;
            const float* wq0 = &s_w[oc0_blk * 73 + ici * 9];
            const float* wq1 = wq0 + 73;
            ull W0[9], W1[9];
            #pragma unroll
            for (int k = 0; k < 9; k++) {
                float a = wq0[k], c_ = wq1[k];
                W0[k] = pk2(a, a); W1[k] = pk2(c_, c_);
            }
            const float* rowb = &s_in[ic * 80 + 2 * cp];
            #pragma unroll
            for (int r = 0; r < 8; r++) {
                ull L = *(const ull*)(rowb + r * 10);
                ull R = *(const ull*)(rowb + r * 10 + 2);
                float2 Lf = upk2(L), Rf = upk2(R);
                ull V = pk2(Lf.y, Rf.x);
                if (r >= 1) {
                    acc0[r - 1] = ff2(W0[6], L, ff2(W0[7], V, ff2(W0[8], R, acc0[r - 1])));
                    acc1[r - 1] = ff2(W1[6], L, ff2(W1[7], V, ff2(W1[8], R, acc1[r - 1])));
                }
                acc0[r] = ff2(W0[3], L, ff2(W0[4], V, ff2(W0[5], R, acc0[r])));
                acc1[r] = ff2(W1[3], L, ff2(W1[4], V, ff2(W1[5], R, acc1[r])));
                if (r <= 6) {
                    acc0[r + 1] = ff2(W0[0], L, ff2(W0[1], V, ff2(W0[2], R, acc0[r + 1])));
                    acc1[r + 1] = ff2(W1[0], L, ff2(W1[1], V, ff2(W1[2], R, acc1[r + 1])));
                }
            }
        }
    }

    // BN + ReLU + 2x2 pool + avg: thread holds 4 pooled rows x 1 pooled col (=cp)
    #pragma unroll
    for (int k = 0; k < 2; k++) {
        const int oc = oc0 + k;
        const ull* ac = k ? acc1 : acc0;
        float inv = gam[oc] * rsqrtf(var[oc] + BN_EPS);
        float sh = (bias[oc] - mean[oc]) * inv + bet[oc];
        float sum = 0.f;
        #pragma unroll
        for (int j = 0; j < 4; j++) {
            float2 a = upk2(ac[2 * j]);
            float2 c = upk2(ac[2 * j + 1]);
            float v00 = fmaxf(fmaf(a.x, inv, sh), 0.f);
            float v01 = fmaxf(fmaf(a.y, inv, sh), 0.f);
            float v10 = fmaxf(fmaf(c.x, inv, sh), 0.f);
            float v11 = fmaxf(fmaf(c.y, inv, sh), 0.f);
            sum += fmaxf(fmaxf(v00, v01), fmaxf(v10, v11));
        }
        sum += __shfl_down_sync(0xffffffffu, sum, 2, 4);
        sum += __shfl_down_sync(0xffffffffu, sum, 1, 4);
        if (cp == 0)
            g_feat[(size_t)b * 128 + oc] = sum * (1.f / 16.f);
    }
}

// =============================================================================
// Stage 4: gate (top-2 softmax) + top-2 expert MLPs, fused. (unchanged, 55us)
// =============================================================================
__global__ __launch_bounds__(256) void moe_kernel(
    const float* __restrict__ w1,   // [8,128,64]
    const float* __restrict__ b1,   // [8,64]
    const float* __restrict__ w2,   // [8,64,10]
    const float* __restrict__ b2,   // [8,10]
    const float* __restrict__ gw,   // [128,8]
    const float* __restrict__ gb,   // [8]
    float* __restrict__ out, int B)
{
    __shared__ float s_feat[8][128];
    __shared__ float s_h[8][64];
    __shared__ float s_log[8][8];

    const int warp = threadIdx.x >> 5;
    const int lane = threadIdx.x & 31;
    const int s = blockIdx.x * 8 + warp;
    if (s >= B) return;

    for (int i = lane; i < 128; i += 32) s_feat[warp][i] = g_feat[(size_t)s * 128 + i];
    __syncwarp();

    if (lane < 8) {
        float a = gb[lane];
        for (int f = 0; f < 128; f++) a += s_feat[warp][f] * gw[f * 8 + lane];
        s_log[warp][lane] = a;
    }
    __syncwarp();

    float lg[8];
    #pragma unroll
    for (int e = 0; e < 8; e++) lg[e] = s_log[warp][e];
    int i0 = 0; float v0 = lg[0];
    #pragma unroll
    for (int e = 1; e < 8; e++) if (lg[e] > v0) { v0 = lg[e]; i0 = e; }
    int i1 = -1; float v1 = -3.402823466e38f;
    #pragma unroll
    for (int e = 0; e < 8; e++) if (e != i0 && lg[e] > v1) { v1 = lg[e]; i1 = e; }
    float e1 = expf(v1 - v0);
    float invs = 1.f / (1.f + e1);
    float wts[2] = { invs, e1 * invs };
    int eidx[2] = { i0, i1 };

    float outk = 0.f;
    for (int t = 0; t < 2; t++) {
        const int e = eidx[t];
        const float* w1e = w1 + (size_t)e * 128 * 64;
        float h0 = b1[e * 64 + lane];
        float h1v = b1[e * 64 + lane + 32];
        for (int f = 0; f < 128; f++) {
            float fv = s_feat[warp][f];
            h0  += fv * w1e[f * 64 + lane];
            h1v += fv * w1e[f * 64 + lane + 32];
        }
        s_h[warp][lane] = fmaxf(h0, 0.f);
        s_h[warp][lane + 32] = fmaxf(h1v, 0.f);
        __syncwarp();
        if (lane < 10) {
            const float* w2e = w2 + e * 640;
            float o = b2[e * 10 + lane];
            for (int j = 0; j < 64; j++) o += s_h[warp][j] * w2e[j * 10 + lane];
            outk += wts[t] * o;
        }
        __syncwarp();
    }
    if (lane < 10) out[(size_t)s * 10 + lane] = outk;
}

// =============================================================================
extern "C" void kernel_launch(void* const* d_in, const int* in_sizes, int n_in,
                              void* d_out, int out_size)
{
    const float* x       = (const float*)d_in[0];
    const float* c1w     = (const float*)d_in[1];
    const float* c1b     = (const float*)d_in[2];
    const float* bn1g    = (const float*)d_in[3];
    const float* bn1b    = (const float*)d_in[4];
    const float* bn1m    = (const float*)d_in[5];
    const float* bn1v    = (const float*)d_in[6];
    const float* c2w     = (const float*)d_in[7];
    const float* c2b     = (const float*)d_in[8];
    const float* bn2g    = (const float*)d_in[9];
    const float* bn2b    = (const float*)d_in[10];
    const float* bn2m    = (const float*)d_in[11];
    const float* bn2v    = (const float*)d_in[12];
    const float* c3w     = (const float*)d_in[13];
    const float* c3b     = (const float*)d_in[14];
    const float* bn3g    = (const float*)d_in[15];
    const float* bn3b    = (const float*)d_in[16];
    const float* bn3m    = (const float*)d_in[17];
    const float* bn3v    = (const float*)d_in[18];
    const float* w1      = (const float*)d_in[19];
    const float* b1      = (const float*)d_in[20];
    const float* w2      = (const float*)d_in[21];
    const float* b2      = (const float*)d_in[22];
    const float* gate_w  = (const float*)d_in[23];
    const float* gate_b  = (const float*)d_in[24];

    int B = in_sizes[0] / (3 * 32 * 32);
    if (B > 4096) B = 4096;

    // two no-op launches: keep ncu's profiled slot (-s 5) on conv2
    dummy_kernel<<<1, 32>>>();
    dummy_kernel<<<1, 32>>>();

    conv1_kernel<<<B, 128>>>(x, c1w, c1b, bn1g, bn1b, bn1m, bn1v);
    conv2_kernel<<<B * 4, 128>>>(c2w, c2b, bn2g, bn2b, bn2m, bn2v);
    conv3_kernel<<<B * 2, 128>>>(c3w, c3b, bn3g, bn3b, bn3m, bn3v);
    moe_kernel<<<(B + 7) / 8, 256>>>(w1, b1, w2, b2, gate_w, gate_b, (float*)d_out, B);
}